// round 2
// baseline (speedup 1.0000x reference)
#include <cuda_runtime.h>

#define BB 4
#define LL 1024
#define DD 512
#define HH 8
#define HDIM 64
#define FF 2048
#define NLAYERS 6
#define ROWS (BB*LL)        // 4096

// ---------------- scratch (no allocation allowed) ----------------
__device__ float g_x[ROWS*DD];
__device__ float g_q[ROWS*DD];
__device__ float g_k[ROWS*DD];
__device__ float g_v[ROWS*DD];
__device__ float g_a[ROWS*DD];
__device__ float g_t[ROWS*DD];   // proj-out / ffn-out staging
__device__ float g_h[ROWS*FF];   // ffn hidden

// ---------------- copy query -> g_x ----------------
__global__ void copy_kernel(const float* __restrict__ src, float* __restrict__ dst, int n4) {
    int i = blockIdx.x * blockDim.x + threadIdx.x;
    if (i < n4) {
        ((float4*)dst)[i] = ((const float4*)src)[i];
    }
}

// ---------------- tiled SGEMM: C[M,N] = A[M,K] @ W[N,K]^T + bias, optional relu ----------------
// 64x64 tile, BK=16, 128 threads, 4x8 microtile per thread
template<bool RELU>
__global__ void gemm_kernel(const float* __restrict__ A, const float* __restrict__ W,
                            const float* __restrict__ bias, float* __restrict__ C,
                            int M, int N, int K) {
    __shared__ float As[64 * 17];
    __shared__ float Bs[64 * 17];
    const int n0 = blockIdx.x * 64;
    const int m0 = blockIdx.y * 64;
    const int tid = threadIdx.x;        // 0..127
    const int grp = tid >> 3;           // 0..15
    const int tx  = tid & 7;            // 0..7
    const int rb  = grp * 4;            // row base (4 rows)
    // cols are interleaved: n = tx + 8*j  (bank-conflict-free Bs reads)

    float acc[4][8];
#pragma unroll
    for (int i = 0; i < 4; i++)
#pragma unroll
        for (int j = 0; j < 8; j++) acc[i][j] = 0.f;

    for (int k0 = 0; k0 < K; k0 += 16) {
        __syncthreads();
#pragma unroll
        for (int it = 0; it < 8; it++) {
            int idx = tid + it * 128;   // 0..1023
            int r = idx >> 4, kk = idx & 15;
            As[r * 17 + kk] = A[(size_t)(m0 + r) * K + k0 + kk];
            Bs[r * 17 + kk] = W[(size_t)(n0 + r) * K + k0 + kk];
        }
        __syncthreads();
#pragma unroll
        for (int kk = 0; kk < 16; kk++) {
            float ra[4], rbv[8];
#pragma unroll
            for (int i = 0; i < 4; i++) ra[i] = As[(rb + i) * 17 + kk];
#pragma unroll
            for (int j = 0; j < 8; j++) rbv[j] = Bs[(tx + 8 * j) * 17 + kk];
#pragma unroll
            for (int i = 0; i < 4; i++)
#pragma unroll
                for (int j = 0; j < 8; j++) acc[i][j] += ra[i] * rbv[j];
        }
    }
#pragma unroll
    for (int j = 0; j < 8; j++) {
        int n = n0 + tx + 8 * j;
        float bv = bias[n];
#pragma unroll
        for (int i = 0; i < 4; i++) {
            float val = acc[i][j] + bv;
            if (RELU) val = fmaxf(val, 0.f);
            C[(size_t)(m0 + rb + i) * N + n] = val;
        }
    }
}

// ---------------- fused flash-style attention ----------------
// grid (L/64, H, B), 256 threads. Each thread: 1 query row (row = tid>>2),
// sub = tid&3 owns S-cols / O-cols c = sub + 4*j (j=0..15).
#define AT_STR 68
#define AT_SMEM ((4 * 64 * AT_STR + 64) * 4)

__global__ void attn_kernel(const float* __restrict__ q, const float* __restrict__ k,
                            const float* __restrict__ v, const float* __restrict__ kmask,
                            float* __restrict__ out) {
    extern __shared__ float sm[];
    float* Qs = sm;                  // [64][68]
    float* Ks = Qs + 64 * AT_STR;
    float* Vs = Ks + 64 * AT_STR;
    float* Ss = Vs + 64 * AT_STR;
    float* KM = Ss + 64 * AT_STR;    // [64]

    const int q0 = blockIdx.x * 64;
    const int h  = blockIdx.y;
    const int b  = blockIdx.z;
    const int tid = threadIdx.x;
    const int row = tid >> 2;
    const int sub = tid & 3;
    const float scale = 0.125f;      // 1/sqrt(64)

    // load Q tile (pre-scaled)
    const float* qbase = q + ((size_t)(b * LL + q0)) * DD + h * HDIM;
#pragma unroll
    for (int i = tid; i < 64 * 16; i += 256) {
        int r = i >> 4, d4 = i & 15;
        float4 val = *(const float4*)(qbase + (size_t)r * DD + d4 * 4);
        val.x *= scale; val.y *= scale; val.z *= scale; val.w *= scale;
        *(float4*)(Qs + r * AT_STR + d4 * 4) = val;
    }

    float o[16];
#pragma unroll
    for (int j = 0; j < 16; j++) o[j] = 0.f;
    float m = -1e30f, l = 0.f;

    for (int kt = 0; kt < LL / 64; kt++) {
        __syncthreads();
        const int k0 = kt * 64;
        const float* kbase = k + ((size_t)(b * LL + k0)) * DD + h * HDIM;
        const float* vbase = v + ((size_t)(b * LL + k0)) * DD + h * HDIM;
#pragma unroll
        for (int i = tid; i < 64 * 16; i += 256) {
            int r = i >> 4, d4 = i & 15;
            *(float4*)(Ks + r * AT_STR + d4 * 4) = *(const float4*)(kbase + (size_t)r * DD + d4 * 4);
            *(float4*)(Vs + r * AT_STR + d4 * 4) = *(const float4*)(vbase + (size_t)r * DD + d4 * 4);
        }
        if (tid < 64) KM[tid] = kmask[b * LL + k0 + tid];
        __syncthreads();

        // --- S = Qrow . K^T for own 16 columns (chunked Q register caching) ---
        float sv[16];
#pragma unroll
        for (int j = 0; j < 16; j++) sv[j] = 0.f;
        const float* qr = Qs + row * AT_STR;
#pragma unroll
        for (int d0 = 0; d0 < 64; d0 += 8) {
            float qv[8];
#pragma unroll
            for (int dd = 0; dd < 8; dd++) qv[dd] = qr[d0 + dd];
#pragma unroll
            for (int j = 0; j < 16; j++) {
                const float* kr = Ks + (sub + 4 * j) * AT_STR + d0;
#pragma unroll
                for (int dd = 0; dd < 8; dd++) sv[j] += qv[dd] * kr[dd];
            }
        }
#pragma unroll
        for (int j = 0; j < 16; j++)
            if (KM[sub + 4 * j] == 0.f) sv[j] = -1e30f;

        // --- online softmax (quad = 4 lanes sharing a row) ---
        float tmax = sv[0];
#pragma unroll
        for (int j = 1; j < 16; j++) tmax = fmaxf(tmax, sv[j]);
        tmax = fmaxf(tmax, __shfl_xor_sync(0xffffffffu, tmax, 1));
        tmax = fmaxf(tmax, __shfl_xor_sync(0xffffffffu, tmax, 2));
        float mnew = fmaxf(m, tmax);
        float corr = __expf(m - mnew);
        l *= corr;
#pragma unroll
        for (int j = 0; j < 16; j++) o[j] *= corr;
        float psum = 0.f;
#pragma unroll
        for (int j = 0; j < 16; j++) {
            float p = (sv[j] < -1e29f) ? 0.f : __expf(sv[j] - mnew);
            psum += p;
            Ss[row * AT_STR + sub + 4 * j] = p;
        }
        psum += __shfl_xor_sync(0xffffffffu, psum, 1);
        psum += __shfl_xor_sync(0xffffffffu, psum, 2);
        l += psum;
        m = mnew;
        __syncwarp();

        // --- O += P @ V (own 16 dv columns dv = sub + 4*j) ---
        const float* sr = Ss + row * AT_STR;
#pragma unroll 8
        for (int c = 0; c < 64; c++) {
            float p = sr[c];
            const float* vr = Vs + c * AT_STR;
#pragma unroll
            for (int j = 0; j < 16; j++) o[j] += p * vr[sub + 4 * j];
        }
    }

    float inv = 1.f / l;
#pragma unroll
    for (int j = 0; j < 16; j++) Ss[row * AT_STR + sub + 4 * j] = o[j] * inv;
    __syncthreads();
    float* obase = out + ((size_t)(b * LL + q0)) * DD + h * HDIM;
#pragma unroll
    for (int i = tid; i < 64 * 16; i += 256) {
        int r = i >> 4, d4 = i & 15;
        *(float4*)(obase + (size_t)r * DD + d4 * 4) = *(const float4*)(Ss + r * AT_STR + d4 * 4);
    }
}

// ---------------- fused residual + mask + LayerNorm ----------------
// x_out = LN(y*qm + x_in); one block per row, 128 threads, 4 elems each
__global__ void add_mask_ln_kernel(const float* __restrict__ y, const float* __restrict__ xin,
                                   const float* __restrict__ qmask,
                                   const float* __restrict__ gam, const float* __restrict__ bet,
                                   float* __restrict__ xout) {
    __shared__ float red[4];
    const int row = blockIdx.x;
    const int tid = threadIdx.x;
    const float qmv = qmask[row];
    const float* yr = y + (size_t)row * DD;
    const float* xr = xin + (size_t)row * DD;

    float vals[4];
    float s = 0.f;
#pragma unroll
    for (int i = 0; i < 4; i++) {
        int idx = tid + i * 128;
        vals[i] = yr[idx] * qmv + xr[idx];
        s += vals[i];
    }
#pragma unroll
    for (int off = 16; off > 0; off >>= 1) s += __shfl_down_sync(0xffffffffu, s, off);
    if ((tid & 31) == 0) red[tid >> 5] = s;
    __syncthreads();
    float mean = (red[0] + red[1] + red[2] + red[3]) * (1.f / DD);

    float s2 = 0.f;
#pragma unroll
    for (int i = 0; i < 4; i++) {
        float d = vals[i] - mean;
        s2 += d * d;
    }
    __syncthreads();   // red reuse
#pragma unroll
    for (int off = 16; off > 0; off >>= 1) s2 += __shfl_down_sync(0xffffffffu, s2, off);
    if ((tid & 31) == 0) red[tid >> 5] = s2;
    __syncthreads();
    float var = (red[0] + red[1] + red[2] + red[3]) * (1.f / DD);
    float inv = rsqrtf(var + 1e-5f);

    float* xo = xout + (size_t)row * DD;
#pragma unroll
    for (int i = 0; i < 4; i++) {
        int idx = tid + i * 128;
        xo[idx] = (vals[i] - mean) * inv * gam[idx] + bet[idx];
    }
}

// ---------------- launch ----------------
extern "C" void kernel_launch(void* const* d_in, const int* in_sizes, int n_in,
                              void* d_out, int out_size) {
    const float* query = (const float*)d_in[0];
    const float* key   = (const float*)d_in[1];
    const float* qmask = (const float*)d_in[2];
    const float* kmask = (const float*)d_in[3];
    const float* Wq = (const float*)d_in[4];
    const float* bq = (const float*)d_in[5];
    const float* Wk = (const float*)d_in[6];
    const float* bk = (const float*)d_in[7];
    const float* Wv = (const float*)d_in[8];
    const float* bv = (const float*)d_in[9];
    const float* Wo = (const float*)d_in[10];
    const float* bo = (const float*)d_in[11];
    const float* W1 = (const float*)d_in[12];
    const float* b1 = (const float*)d_in[13];
    const float* W2 = (const float*)d_in[14];
    const float* b2 = (const float*)d_in[15];
    const float* ln1g = (const float*)d_in[16];
    const float* ln1b = (const float*)d_in[17];
    const float* ln2g = (const float*)d_in[18];
    const float* ln2b = (const float*)d_in[19];
    float* out = (float*)d_out;

    float *px, *pq, *pk, *pv, *pa, *pt, *ph;
    cudaGetSymbolAddress((void**)&px, g_x);
    cudaGetSymbolAddress((void**)&pq, g_q);
    cudaGetSymbolAddress((void**)&pk, g_k);
    cudaGetSymbolAddress((void**)&pv, g_v);
    cudaGetSymbolAddress((void**)&pa, g_a);
    cudaGetSymbolAddress((void**)&pt, g_t);
    cudaGetSymbolAddress((void**)&ph, g_h);

    cudaFuncSetAttribute(attn_kernel, cudaFuncAttributeMaxDynamicSharedMemorySize, AT_SMEM);

    // x = query
    copy_kernel<<<(ROWS * DD / 4 + 255) / 256, 256>>>(query, px, ROWS * DD / 4);

    const dim3 gemm_blk(128);
    const dim3 gD(DD / 64, ROWS / 64);     // N=512
    const dim3 gF(FF / 64, ROWS / 64);     // N=2048
    const dim3 gAttn(LL / 64, HH, BB);

    for (int li = 0; li < NLAYERS; li++) {
        const size_t wED = (size_t)li * DD * DD;    // E==D==512
        const size_t wFD = (size_t)li * FF * DD;

        gemm_kernel<false><<<gD, gemm_blk>>>(px,  Wq + wED, bq + li * DD, pq, ROWS, DD, DD);
        gemm_kernel<false><<<gD, gemm_blk>>>(key, Wk + wED, bk + li * DD, pk, ROWS, DD, DD);
        gemm_kernel<false><<<gD, gemm_blk>>>(key, Wv + wED, bv + li * DD, pv, ROWS, DD, DD);

        attn_kernel<<<gAttn, 256, AT_SMEM>>>(pq, pk, pv, kmask, pa);

        gemm_kernel<false><<<gD, gemm_blk>>>(pa, Wo + wED, bo + li * DD, pt, ROWS, DD, DD);
        add_mask_ln_kernel<<<ROWS, 128>>>(pt, px, qmask, ln1g + li * DD, ln1b + li * DD, px);

        gemm_kernel<true ><<<gF, gemm_blk>>>(px, W1 + wFD, b1 + li * FF, ph, ROWS, FF, DD);
        gemm_kernel<false><<<gD, gemm_blk>>>(ph, W2 + wFD, b2 + li * DD, pt, ROWS, DD, FF);

        float* dst = (li == NLAYERS - 1) ? out : px;
        add_mask_ln_kernel<<<ROWS, 128>>>(pt, px, qmask, ln2g + li * DD, ln2b + li * DD, dst);
    }
}

// round 5
// speedup vs baseline: 1.9736x; 1.9736x over previous
#include <cuda_runtime.h>
#include <cuda_fp16.h>
#include <cstdint>

#define BB 4
#define LL 1024
#define DD 512
#define HH 8
#define HDIM 64
#define FF 2048
#define NLAYERS 6
#define ROWS (BB*LL)        // 4096

// ---------------- scratch (no allocation allowed) ----------------
__device__ float g_x[ROWS*DD];
__device__ float g_q[ROWS*DD];
__device__ float g_k[ROWS*DD];
__device__ float g_v[ROWS*DD];
__device__ float g_t[ROWS*DD];
__device__ __half g_xh[ROWS*DD];
__device__ __half g_kh[ROWS*DD];
__device__ __half g_ah[ROWS*DD];
__device__ __half g_hh[ROWS*FF];
__device__ __half g_wqh[NLAYERS*DD*DD];
__device__ __half g_wkh[NLAYERS*DD*DD];
__device__ __half g_wvh[NLAYERS*DD*DD];
__device__ __half g_woh[NLAYERS*DD*DD];
__device__ __half g_w1h[NLAYERS*FF*DD];
__device__ __half g_w2h[NLAYERS*FF*DD];

// ---------------- helpers ----------------
__device__ __forceinline__ uint32_t smem_u32(const void* p) {
    uint32_t a;
    asm("{ .reg .u64 t; cvta.to.shared.u64 t, %1; cvt.u32.u64 %0, t; }" : "=r"(a) : "l"(p));
    return a;
}
__device__ __forceinline__ void cp_async16(uint32_t dst, const void* src) {
    asm volatile("cp.async.cg.shared.global [%0], [%1], 16;" :: "r"(dst), "l"(src) : "memory");
}
__device__ __forceinline__ void cp_commit() {
    asm volatile("cp.async.commit_group;" ::: "memory");
}
template<int N>
__device__ __forceinline__ void cp_wait() {
    asm volatile("cp.async.wait_group %0;" :: "n"(N) : "memory");
}
__device__ __forceinline__ void ldm_x4(uint32_t* r, uint32_t addr) {
    asm volatile("ldmatrix.sync.aligned.m8n8.x4.shared.b16 {%0,%1,%2,%3}, [%4];"
                 : "=r"(r[0]), "=r"(r[1]), "=r"(r[2]), "=r"(r[3]) : "r"(addr));
}
__device__ __forceinline__ void mma16816(float* c, const uint32_t* a, const uint32_t* b) {
    asm volatile(
        "mma.sync.aligned.m16n8k16.row.col.f32.f16.f16.f32 "
        "{%0,%1,%2,%3}, {%4,%5,%6,%7}, {%8,%9}, {%0,%1,%2,%3};"
        : "+f"(c[0]), "+f"(c[1]), "+f"(c[2]), "+f"(c[3])
        : "r"(a[0]), "r"(a[1]), "r"(a[2]), "r"(a[3]), "r"(b[0]), "r"(b[1]));
}

// ---------------- conversion kernels ----------------
__global__ void f2h_kernel(const float* __restrict__ s, __half* __restrict__ d, int n4) {
    int i = blockIdx.x * blockDim.x + threadIdx.x;
    if (i < n4) {
        float4 v = ((const float4*)s)[i];
        __half2* d2 = (__half2*)d + (size_t)i * 2;
        d2[0] = __floats2half2_rn(v.x, v.y);
        d2[1] = __floats2half2_rn(v.z, v.w);
    }
}
__global__ void copy_both_kernel(const float* __restrict__ s, float* __restrict__ d,
                                 __half* __restrict__ dh, int n4) {
    int i = blockIdx.x * blockDim.x + threadIdx.x;
    if (i < n4) {
        float4 v = ((const float4*)s)[i];
        ((float4*)d)[i] = v;
        __half2* d2 = (__half2*)dh + (size_t)i * 2;
        d2[0] = __floats2half2_rn(v.x, v.y);
        d2[1] = __floats2half2_rn(v.z, v.w);
    }
}

// ---------------- HMMA fp16 GEMM: C[M,N] = A[M,K] @ W[N,K]^T + bias ----------------
// 128x128 tile, BK=32, 256 threads (8 warps: 4m x 2n), warp tile 32x64,
// cp.async double buffer, smem stride 40 halfs (conflict-free ldmatrix).
#define GSTR 40
#define STAGE_HALFS (128 * GSTR * 2)    // A then B per stage

template<bool RELU, bool OUTH>
__global__ __launch_bounds__(256)
void gemm_tc(const __half* __restrict__ A, const __half* __restrict__ Wt,
             const float* __restrict__ bias, void* __restrict__ Cout,
             int M, int N, int K) {
    __shared__ __half sh[2 * STAGE_HALFS];
    const uint32_t sb = smem_u32(sh);
    const int tid = threadIdx.x;
    const int wid = tid >> 5;
    const int lane = tid & 31;
    const int m0 = blockIdx.y * 128;
    const int n0 = blockIdx.x * 128;

    const int mwb = (wid >> 1) * 32;    // warp m base
    const int nwb = (wid & 1) * 64;     // warp n base

    // load mapping: 4 chunks of 16B per thread per stage
    // chunk idx = tid + it*256; idx<512 -> A, else B; r = (idx&511)>>2, cseg = idx&3
    float c[2][8][4];
#pragma unroll
    for (int mt = 0; mt < 2; mt++)
#pragma unroll
        for (int nt = 0; nt < 8; nt++)
#pragma unroll
            for (int i = 0; i < 4; i++) c[mt][nt][i] = 0.f;

    const int nch = K >> 5;

    auto load_stage = [&](int kc, int stage) {
        const uint32_t sbase = sb + stage * STAGE_HALFS * 2;
#pragma unroll
        for (int it = 0; it < 4; it++) {
            int idx = tid + it * 256;
            int r = (idx & 511) >> 2;
            int cseg = idx & 3;
            const __half* src;
            uint32_t dst;
            if (idx < 512) {
                src = A + (size_t)(m0 + r) * K + kc * 32 + cseg * 8;
                dst = sbase + (r * GSTR + cseg * 8) * 2;
            } else {
                src = Wt + (size_t)(n0 + r) * K + kc * 32 + cseg * 8;
                dst = sbase + (128 * GSTR + r * GSTR + cseg * 8) * 2;
            }
            cp_async16(dst, src);
        }
        cp_commit();
    };

    load_stage(0, 0);

    for (int kc = 0; kc < nch; kc++) {
        const int stage = kc & 1;
        if (kc + 1 < nch) {
            load_stage(kc + 1, stage ^ 1);
            cp_wait<1>();
        } else {
            cp_wait<0>();
        }
        __syncthreads();

        const uint32_t Ab = sb + stage * STAGE_HALFS * 2;
        const uint32_t Bb = Ab + 128 * GSTR * 2;

#pragma unroll
        for (int ks = 0; ks < 2; ks++) {
            uint32_t afr[2][4], bfr[4][4];
#pragma unroll
            for (int mt = 0; mt < 2; mt++) {
                uint32_t addr = Ab + (((mwb + mt * 16 + (lane & 15)) * GSTR)
                                      + ks * 16 + ((lane >> 4) << 3)) * 2;
                ldm_x4(afr[mt], addr);
            }
#pragma unroll
            for (int np = 0; np < 4; np++) {
                uint32_t addr = Bb + (((nwb + np * 16 + (lane & 7) + ((lane >> 4) << 3)) * GSTR)
                                      + ks * 16 + (((lane >> 3) & 1) << 3)) * 2;
                ldm_x4(bfr[np], addr);
            }
#pragma unroll
            for (int mt = 0; mt < 2; mt++)
#pragma unroll
                for (int nt = 0; nt < 8; nt++)
                    mma16816(c[mt][nt], afr[mt], bfr[nt >> 1] + (nt & 1) * 2);
        }
        __syncthreads();
    }

    // ---- epilogue: registers -> gmem with bias (+relu) ----
#pragma unroll
    for (int mt = 0; mt < 2; mt++) {
#pragma unroll
        for (int nt = 0; nt < 8; nt++) {
            int col = n0 + nwb + nt * 8 + (lane & 3) * 2;
            float bv0 = bias[col], bv1 = bias[col + 1];
            int r0 = m0 + mwb + mt * 16 + (lane >> 2);
            float v0 = c[mt][nt][0] + bv0;
            float v1 = c[mt][nt][1] + bv1;
            float v2 = c[mt][nt][2] + bv0;
            float v3 = c[mt][nt][3] + bv1;
            if (RELU) {
                v0 = fmaxf(v0, 0.f); v1 = fmaxf(v1, 0.f);
                v2 = fmaxf(v2, 0.f); v3 = fmaxf(v3, 0.f);
            }
            if (OUTH) {
                __half* base = (__half*)Cout;
                *(__half2*)(base + (size_t)r0 * N + col)       = __floats2half2_rn(v0, v1);
                *(__half2*)(base + (size_t)(r0 + 8) * N + col) = __floats2half2_rn(v2, v3);
            } else {
                float* base = (float*)Cout;
                *(float2*)(base + (size_t)r0 * N + col)       = make_float2(v0, v1);
                *(float2*)(base + (size_t)(r0 + 8) * N + col) = make_float2(v2, v3);
            }
        }
    }
}

// ---------------- fused flash-style attention (fp32 compute, fp16 output) ----------------
#define AT_STR 68
#define AT_SMEM ((4 * 64 * AT_STR + 64) * 4)

__global__ void attn_kernel(const float* __restrict__ q, const float* __restrict__ k,
                            const float* __restrict__ v, const float* __restrict__ kmask,
                            __half* __restrict__ out) {
    extern __shared__ float sm[];
    float* Qs = sm;
    float* Ks = Qs + 64 * AT_STR;
    float* Vs = Ks + 64 * AT_STR;
    float* Ss = Vs + 64 * AT_STR;
    float* KM = Ss + 64 * AT_STR;

    const int q0 = blockIdx.x * 64;
    const int h  = blockIdx.y;
    const int b  = blockIdx.z;
    const int tid = threadIdx.x;
    const int row = tid >> 2;
    const int sub = tid & 3;
    const float scale = 0.125f;

    const float* qbase = q + ((size_t)(b * LL + q0)) * DD + h * HDIM;
#pragma unroll
    for (int i = tid; i < 64 * 16; i += 256) {
        int r = i >> 4, d4 = i & 15;
        float4 val = *(const float4*)(qbase + (size_t)r * DD + d4 * 4);
        val.x *= scale; val.y *= scale; val.z *= scale; val.w *= scale;
        *(float4*)(Qs + r * AT_STR + d4 * 4) = val;
    }

    float o[16];
#pragma unroll
    for (int j = 0; j < 16; j++) o[j] = 0.f;
    float m = -1e30f, l = 0.f;

    for (int kt = 0; kt < LL / 64; kt++) {
        __syncthreads();
        const int k0 = kt * 64;
        const float* kbase = k + ((size_t)(b * LL + k0)) * DD + h * HDIM;
        const float* vbase = v + ((size_t)(b * LL + k0)) * DD + h * HDIM;
#pragma unroll
        for (int i = tid; i < 64 * 16; i += 256) {
            int r = i >> 4, d4 = i & 15;
            *(float4*)(Ks + r * AT_STR + d4 * 4) = *(const float4*)(kbase + (size_t)r * DD + d4 * 4);
            *(float4*)(Vs + r * AT_STR + d4 * 4) = *(const float4*)(vbase + (size_t)r * DD + d4 * 4);
        }
        if (tid < 64) KM[tid] = kmask[b * LL + k0 + tid];
        __syncthreads();

        float sv[16];
#pragma unroll
        for (int j = 0; j < 16; j++) sv[j] = 0.f;
        const float* qr = Qs + row * AT_STR;
#pragma unroll
        for (int d0 = 0; d0 < 64; d0 += 8) {
            float qv[8];
#pragma unroll
            for (int dd = 0; dd < 8; dd++) qv[dd] = qr[d0 + dd];
#pragma unroll
            for (int j = 0; j < 16; j++) {
                const float* kr = Ks + (sub + 4 * j) * AT_STR + d0;
#pragma unroll
                for (int dd = 0; dd < 8; dd++) sv[j] += qv[dd] * kr[dd];
            }
        }
#pragma unroll
        for (int j = 0; j < 16; j++)
            if (KM[sub + 4 * j] == 0.f) sv[j] = -1e30f;

        float tmax = sv[0];
#pragma unroll
        for (int j = 1; j < 16; j++) tmax = fmaxf(tmax, sv[j]);
        tmax = fmaxf(tmax, __shfl_xor_sync(0xffffffffu, tmax, 1));
        tmax = fmaxf(tmax, __shfl_xor_sync(0xffffffffu, tmax, 2));
        float mnew = fmaxf(m, tmax);
        float corr = __expf(m - mnew);
        l *= corr;
#pragma unroll
        for (int j = 0; j < 16; j++) o[j] *= corr;
        float psum = 0.f;
#pragma unroll
        for (int j = 0; j < 16; j++) {
            float p = (sv[j] < -1e29f) ? 0.f : __expf(sv[j] - mnew);
            psum += p;
            Ss[row * AT_STR + sub + 4 * j] = p;
        }
        psum += __shfl_xor_sync(0xffffffffu, psum, 1);
        psum += __shfl_xor_sync(0xffffffffu, psum, 2);
        l += psum;
        m = mnew;
        __syncwarp();

        const float* sr = Ss + row * AT_STR;
#pragma unroll 8
        for (int cc = 0; cc < 64; cc++) {
            float p = sr[cc];
            const float* vr = Vs + cc * AT_STR;
#pragma unroll
            for (int j = 0; j < 16; j++) o[j] += p * vr[sub + 4 * j];
        }
    }

    float inv = 1.f / l;
#pragma unroll
    for (int j = 0; j < 16; j++) Ss[row * AT_STR + sub + 4 * j] = o[j] * inv;
    __syncthreads();
    __half* obase = out + ((size_t)(b * LL + q0)) * DD + h * HDIM;
#pragma unroll
    for (int i = tid; i < 64 * 16; i += 256) {
        int r = i >> 4, d4 = i & 15;
        const float* src = Ss + r * AT_STR + d4 * 4;
        __half* dst = obase + (size_t)r * DD + d4 * 4;
        *(__half2*)dst       = __floats2half2_rn(src[0], src[1]);
        *(__half2*)(dst + 2) = __floats2half2_rn(src[2], src[3]);
    }
}

// ---------------- fused residual + mask + LayerNorm (fp32 + fp16 outputs) ----------------
__global__ void add_mask_ln_kernel(const float* __restrict__ y, const float* __restrict__ xin,
                                   const float* __restrict__ qmask,
                                   const float* __restrict__ gam, const float* __restrict__ bet,
                                   float* __restrict__ xout, __half* __restrict__ xouth) {
    __shared__ float red[4];
    const int row = blockIdx.x;
    const int tid = threadIdx.x;
    const float qmv = qmask[row];
    const float* yr = y + (size_t)row * DD;
    const float* xr = xin + (size_t)row * DD;

    float vals[4];
    float s = 0.f;
#pragma unroll
    for (int i = 0; i < 4; i++) {
        int idx = tid + i * 128;
        vals[i] = yr[idx] * qmv + xr[idx];
        s += vals[i];
    }
#pragma unroll
    for (int off = 16; off > 0; off >>= 1) s += __shfl_down_sync(0xffffffffu, s, off);
    if ((tid & 31) == 0) red[tid >> 5] = s;
    __syncthreads();
    float mean = (red[0] + red[1] + red[2] + red[3]) * (1.f / DD);

    float s2 = 0.f;
#pragma unroll
    for (int i = 0; i < 4; i++) {
        float d = vals[i] - mean;
        s2 += d * d;
    }
    __syncthreads();
#pragma unroll
    for (int off = 16; off > 0; off >>= 1) s2 += __shfl_down_sync(0xffffffffu, s2, off);
    if ((tid & 31) == 0) red[tid >> 5] = s2;
    __syncthreads();
    float var = (red[0] + red[1] + red[2] + red[3]) * (1.f / DD);
    float inv = rsqrtf(var + 1e-5f);

    float* xo = xout + (size_t)row * DD;
    __half* xoh = xouth + (size_t)row * DD;
#pragma unroll
    for (int i = 0; i < 4; i++) {
        int idx = tid + i * 128;
        float r = (vals[i] - mean) * inv * gam[idx] + bet[idx];
        xo[idx] = r;
        xoh[idx] = __float2half(r);
    }
}

// ---------------- launch ----------------
extern "C" void kernel_launch(void* const* d_in, const int* in_sizes, int n_in,
                              void* d_out, int out_size) {
    const float* query = (const float*)d_in[0];
    const float* key   = (const float*)d_in[1];
    const float* qmask = (const float*)d_in[2];
    const float* kmask = (const float*)d_in[3];
    const float* bq = (const float*)d_in[5];
    const float* bk = (const float*)d_in[7];
    const float* bv = (const float*)d_in[9];
    const float* bo = (const float*)d_in[11];
    const float* b1 = (const float*)d_in[13];
    const float* b2 = (const float*)d_in[15];
    const float* ln1g = (const float*)d_in[16];
    const float* ln1b = (const float*)d_in[17];
    const float* ln2g = (const float*)d_in[18];
    const float* ln2b = (const float*)d_in[19];
    float* out = (float*)d_out;

    float *px, *pq, *pk, *pv, *pt;
    __half *pxh, *pkh, *pah, *phh;
    __half *wq, *wk, *wv, *wo, *w1, *w2;
    cudaGetSymbolAddress((void**)&px, g_x);
    cudaGetSymbolAddress((void**)&pq, g_q);
    cudaGetSymbolAddress((void**)&pk, g_k);
    cudaGetSymbolAddress((void**)&pv, g_v);
    cudaGetSymbolAddress((void**)&pt, g_t);
    cudaGetSymbolAddress((void**)&pxh, g_xh);
    cudaGetSymbolAddress((void**)&pkh, g_kh);
    cudaGetSymbolAddress((void**)&pah, g_ah);
    cudaGetSymbolAddress((void**)&phh, g_hh);
    cudaGetSymbolAddress((void**)&wq, g_wqh);
    cudaGetSymbolAddress((void**)&wk, g_wkh);
    cudaGetSymbolAddress((void**)&wv, g_wvh);
    cudaGetSymbolAddress((void**)&wo, g_woh);
    cudaGetSymbolAddress((void**)&w1, g_w1h);
    cudaGetSymbolAddress((void**)&w2, g_w2h);

    cudaFuncSetAttribute(attn_kernel, cudaFuncAttributeMaxDynamicSharedMemorySize, AT_SMEM);

    // weight + input conversions
    {
        int nD = NLAYERS * DD * DD / 4;
        int nF = NLAYERS * FF * DD / 4;
        f2h_kernel<<<(nD + 255) / 256, 256>>>((const float*)d_in[4],  wq, nD);
        f2h_kernel<<<(nD + 255) / 256, 256>>>((const float*)d_in[6],  wk, nD);
        f2h_kernel<<<(nD + 255) / 256, 256>>>((const float*)d_in[8],  wv, nD);
        f2h_kernel<<<(nD + 255) / 256, 256>>>((const float*)d_in[10], wo, nD);
        f2h_kernel<<<(nF + 255) / 256, 256>>>((const float*)d_in[12], w1, nF);
        f2h_kernel<<<(nF + 255) / 256, 256>>>((const float*)d_in[14], w2, nF);
        int nX = ROWS * DD / 4;
        f2h_kernel<<<(nX + 255) / 256, 256>>>(key, pkh, nX);
        copy_both_kernel<<<(nX + 255) / 256, 256>>>(query, px, pxh, nX);
    }

    const dim3 gemm_blk(256);
    const dim3 gD(DD / 128, ROWS / 128);   // 4 x 32
    const dim3 gF(FF / 128, ROWS / 128);   // 16 x 32
    const dim3 gAttn(LL / 64, HH, BB);

    for (int li = 0; li < NLAYERS; li++) {
        const size_t wED = (size_t)li * DD * DD;
        const size_t wFD = (size_t)li * FF * DD;

        gemm_tc<false, false><<<gD, gemm_blk>>>(pxh, wq + wED, bq + li * DD, pq, ROWS, DD, DD);
        gemm_tc<false, false><<<gD, gemm_blk>>>(pkh, wk + wED, bk + li * DD, pk, ROWS, DD, DD);
        gemm_tc<false, false><<<gD, gemm_blk>>>(pkh, wv + wED, bv + li * DD, pv, ROWS, DD, DD);

        attn_kernel<<<gAttn, 256, AT_SMEM>>>(pq, pk, pv, kmask, pah);

        gemm_tc<false, false><<<gD, gemm_blk>>>(pah, wo + wED, bo + li * DD, pt, ROWS, DD, DD);
        add_mask_ln_kernel<<<ROWS, 128>>>(pt, px, qmask, ln1g + li * DD, ln1b + li * DD, px, pxh);

        gemm_tc<true, true><<<gF, gemm_blk>>>(pxh, w1 + wFD, b1 + li * FF, phh, ROWS, FF, DD);
        gemm_tc<false, false><<<gD, gemm_blk>>>(phh, w2 + wFD, b2 + li * DD, pt, ROWS, DD, FF);

        float* dst = (li == NLAYERS - 1) ? out : px;
        add_mask_ln_kernel<<<ROWS, 128>>>(pt, px, qmask, ln2g + li * DD, ln2b + li * DD, dst, pxh);
    }
}

// round 7
// speedup vs baseline: 7.4589x; 3.7794x over previous
#include <cuda_runtime.h>
#include <cuda_fp16.h>
#include <cstdint>

#define BB 4
#define LL 1024
#define DD 512
#define HH 8
#define HDIM 64
#define FF 2048
#define NLAYERS 6
#define ROWS (BB*LL)        // 4096

// ---------------- scratch (no allocation allowed) ----------------
__device__ float g_x[ROWS*DD];
__device__ float g_t[ROWS*DD];
__device__ __half g_qh[ROWS*DD];
__device__ __half g_kvh[2*ROWS*DD];
__device__ __half g_xh[ROWS*DD];
__device__ __half g_kh[ROWS*DD];
__device__ __half g_ah[ROWS*DD];
__device__ __half g_hh[ROWS*FF];
__device__ __half g_wqh[NLAYERS*DD*DD];
__device__ __half g_wkh[NLAYERS*DD*DD];
__device__ __half g_wvh[NLAYERS*DD*DD];
__device__ __half g_woh[NLAYERS*DD*DD];
__device__ __half g_w1h[NLAYERS*FF*DD];
__device__ __half g_w2h[NLAYERS*FF*DD];

// ---------------- helpers ----------------
__device__ __forceinline__ uint32_t smem_u32(const void* p) {
    uint32_t a;
    asm("{ .reg .u64 t; cvta.to.shared.u64 t, %1; cvt.u32.u64 %0, t; }" : "=r"(a) : "l"(p));
    return a;
}
__device__ __forceinline__ void cp_async16(uint32_t dst, const void* src) {
    asm volatile("cp.async.cg.shared.global [%0], [%1], 16;" :: "r"(dst), "l"(src) : "memory");
}
__device__ __forceinline__ void cp_commit() {
    asm volatile("cp.async.commit_group;" ::: "memory");
}
template<int N>
__device__ __forceinline__ void cp_wait() {
    asm volatile("cp.async.wait_group %0;" :: "n"(N) : "memory");
}
__device__ __forceinline__ void ldm_x4(uint32_t* r, uint32_t addr) {
    asm volatile("ldmatrix.sync.aligned.m8n8.x4.shared.b16 {%0,%1,%2,%3}, [%4];"
                 : "=r"(r[0]), "=r"(r[1]), "=r"(r[2]), "=r"(r[3]) : "r"(addr));
}
__device__ __forceinline__ void ldm_x4_t(uint32_t* r, uint32_t addr) {
    asm volatile("ldmatrix.sync.aligned.m8n8.x4.trans.shared.b16 {%0,%1,%2,%3}, [%4];"
                 : "=r"(r[0]), "=r"(r[1]), "=r"(r[2]), "=r"(r[3]) : "r"(addr));
}
__device__ __forceinline__ void mma16816(float* c, const uint32_t* a, const uint32_t* b) {
    asm volatile(
        "mma.sync.aligned.m16n8k16.row.col.f32.f16.f16.f32 "
        "{%0,%1,%2,%3}, {%4,%5,%6,%7}, {%8,%9}, {%0,%1,%2,%3};"
        : "+f"(c[0]), "+f"(c[1]), "+f"(c[2]), "+f"(c[3])
        : "r"(a[0]), "r"(a[1]), "r"(a[2]), "r"(a[3]), "r"(b[0]), "r"(b[1]));
}
__device__ __forceinline__ uint32_t packh2(float a, float b) {
    __half2 h = __floats2half2_rn(a, b);
    return *(uint32_t*)&h;
}

// ---------------- conversion kernels ----------------
__global__ void f2h_kernel(const float* __restrict__ s, __half* __restrict__ d, int n4) {
    int i = blockIdx.x * blockDim.x + threadIdx.x;
    if (i < n4) {
        float4 v = ((const float4*)s)[i];
        __half2* d2 = (__half2*)d + (size_t)i * 2;
        d2[0] = __floats2half2_rn(v.x, v.y);
        d2[1] = __floats2half2_rn(v.z, v.w);
    }
}
__global__ void copy_both_kernel(const float* __restrict__ s, float* __restrict__ d,
                                 __half* __restrict__ dh, int n4) {
    int i = blockIdx.x * blockDim.x + threadIdx.x;
    if (i < n4) {
        float4 v = ((const float4*)s)[i];
        ((float4*)d)[i] = v;
        __half2* d2 = (__half2*)dh + (size_t)i * 2;
        d2[0] = __floats2half2_rn(v.x, v.y);
        d2[1] = __floats2half2_rn(v.z, v.w);
    }
}

// ---------------- HMMA fp16 GEMM: C[M,N] = A[M,K] @ W[N,K]^T + bias ----------------
#define GSTR 40
#define STAGE_HALFS (128 * GSTR * 2)

template<bool RELU, bool OUTH>
__global__ __launch_bounds__(256)
void gemm_tc(const __half* __restrict__ A, const __half* __restrict__ Wt,
             const float* __restrict__ bias, void* __restrict__ Cout,
             int M, int N, int K) {
    __shared__ __half sh[2 * STAGE_HALFS];
    const uint32_t sb = smem_u32(sh);
    const int tid = threadIdx.x;
    const int wid = tid >> 5;
    const int lane = tid & 31;
    const int m0 = blockIdx.y * 128;
    const int n0 = blockIdx.x * 128;

    const int mwb = (wid >> 1) * 32;
    const int nwb = (wid & 1) * 64;

    float c[2][8][4];
#pragma unroll
    for (int mt = 0; mt < 2; mt++)
#pragma unroll
        for (int nt = 0; nt < 8; nt++)
#pragma unroll
            for (int i = 0; i < 4; i++) c[mt][nt][i] = 0.f;

    const int nch = K >> 5;

    auto load_stage = [&](int kc, int stage) {
        const uint32_t sbase = sb + stage * STAGE_HALFS * 2;
#pragma unroll
        for (int it = 0; it < 4; it++) {
            int idx = tid + it * 256;
            int r = (idx & 511) >> 2;
            int cseg = idx & 3;
            const __half* src;
            uint32_t dst;
            if (idx < 512) {
                src = A + (size_t)(m0 + r) * K + kc * 32 + cseg * 8;
                dst = sbase + (r * GSTR + cseg * 8) * 2;
            } else {
                src = Wt + (size_t)(n0 + r) * K + kc * 32 + cseg * 8;
                dst = sbase + (128 * GSTR + r * GSTR + cseg * 8) * 2;
            }
            cp_async16(dst, src);
        }
        cp_commit();
    };

    load_stage(0, 0);

    for (int kc = 0; kc < nch; kc++) {
        const int stage = kc & 1;
        if (kc + 1 < nch) {
            load_stage(kc + 1, stage ^ 1);
            cp_wait<1>();
        } else {
            cp_wait<0>();
        }
        __syncthreads();

        const uint32_t Ab = sb + stage * STAGE_HALFS * 2;
        const uint32_t Bb = Ab + 128 * GSTR * 2;

#pragma unroll
        for (int ks = 0; ks < 2; ks++) {
            uint32_t afr[2][4], bfr[4][4];
#pragma unroll
            for (int mt = 0; mt < 2; mt++) {
                uint32_t addr = Ab + (((mwb + mt * 16 + (lane & 15)) * GSTR)
                                      + ks * 16 + ((lane >> 4) << 3)) * 2;
                ldm_x4(afr[mt], addr);
            }
#pragma unroll
            for (int np = 0; np < 4; np++) {
                uint32_t addr = Bb + (((nwb + np * 16 + (lane & 7) + ((lane >> 4) << 3)) * GSTR)
                                      + ks * 16 + (((lane >> 3) & 1) << 3)) * 2;
                ldm_x4(bfr[np], addr);
            }
#pragma unroll
            for (int mt = 0; mt < 2; mt++)
#pragma unroll
                for (int nt = 0; nt < 8; nt++)
                    mma16816(c[mt][nt], afr[mt], bfr[nt >> 1] + (nt & 1) * 2);
        }
        __syncthreads();
    }

#pragma unroll
    for (int mt = 0; mt < 2; mt++) {
#pragma unroll
        for (int nt = 0; nt < 8; nt++) {
            int col = n0 + nwb + nt * 8 + (lane & 3) * 2;
            float bv0 = bias[col], bv1 = bias[col + 1];
            int r0 = m0 + mwb + mt * 16 + (lane >> 2);
            float v0 = c[mt][nt][0] + bv0;
            float v1 = c[mt][nt][1] + bv1;
            float v2 = c[mt][nt][2] + bv0;
            float v3 = c[mt][nt][3] + bv1;
            if (RELU) {
                v0 = fmaxf(v0, 0.f); v1 = fmaxf(v1, 0.f);
                v2 = fmaxf(v2, 0.f); v3 = fmaxf(v3, 0.f);
            }
            if (OUTH) {
                __half* base = (__half*)Cout;
                *(__half2*)(base + (size_t)r0 * N + col)       = __floats2half2_rn(v0, v1);
                *(__half2*)(base + (size_t)(r0 + 8) * N + col) = __floats2half2_rn(v2, v3);
            } else {
                float* base = (float*)Cout;
                *(float2*)(base + (size_t)r0 * N + col)       = make_float2(v0, v1);
                *(float2*)(base + (size_t)(r0 + 8) * N + col) = make_float2(v2, v3);
            }
        }
    }
}

// ---------------- HMMA flash attention ----------------
// grid (L/64, H, B), 128 threads (4 warps), each warp 16 q-rows.
// K iter = 64 keys: S = Q K^T (HMMA), online softmax (fp32), O += P V (HMMA).
#define ATS 72

__global__ __launch_bounds__(128)
void attn_tc(const __half* __restrict__ q, const __half* __restrict__ k,
             const __half* __restrict__ v, const float* __restrict__ kmask,
             __half* __restrict__ out) {
    __shared__ __half Qs[64 * ATS];
    __shared__ __half Ks[2][64 * ATS];
    __shared__ __half Vs[2][64 * ATS];
    __shared__ float MD[2][64];

    const int q0 = blockIdx.x * 64;
    const int h  = blockIdx.y;
    const int b  = blockIdx.z;
    const int tid = threadIdx.x;
    const int wid = tid >> 5;
    const int lane = tid & 31;
    const int mwb = wid * 16;
    const float scl = 0.125f;

    const uint32_t sQ = smem_u32(Qs);
    const uint32_t sK0 = smem_u32(Ks);
    const uint32_t sV0 = smem_u32(Vs);

    // Q tile load (cp.async): 64 rows x 64 halfs
    const __half* qb = q + ((size_t)(b * LL + q0)) * DD + h * HDIM;
#pragma unroll
    for (int i = 0; i < 4; i++) {
        int idx = tid + i * 128;
        int r = idx >> 3, c8 = (idx & 7) * 8;
        cp_async16(sQ + (r * ATS + c8) * 2, qb + (size_t)r * DD + c8);
    }
    cp_commit();

    auto load_kv = [&](int kt, int st) {
        const int k0 = kt * 64;
        const __half* kb = k + ((size_t)(b * LL + k0)) * DD + h * HDIM;
        const __half* vb = v + ((size_t)(b * LL + k0)) * DD + h * HDIM;
        const uint32_t sK = sK0 + st * 64 * ATS * 2;
        const uint32_t sV = sV0 + st * 64 * ATS * 2;
#pragma unroll
        for (int i = 0; i < 8; i++) {
            int idx = tid + i * 128;
            int r = (idx & 511) >> 3, c8 = (idx & 7) * 8;
            if (idx < 512) cp_async16(sK + (r * ATS + c8) * 2, kb + (size_t)r * DD + c8);
            else           cp_async16(sV + (r * ATS + c8) * 2, vb + (size_t)r * DD + c8);
        }
        if (tid < 64) MD[st][tid] = (kmask[b * LL + k0 + tid] == 0.f) ? -1e30f : 0.f;
        cp_commit();
    };

    load_kv(0, 0);
    cp_wait<1>();          // Q ready
    __syncthreads();

    // Q a-fragments (persist whole kernel)
    uint32_t aq[4][4];
#pragma unroll
    for (int kc = 0; kc < 4; kc++) {
        uint32_t addr = sQ + (((mwb + (lane & 15)) * ATS) + kc * 16 + ((lane >> 4) << 3)) * 2;
        ldm_x4(aq[kc], addr);
    }

    float co[8][4];
#pragma unroll
    for (int nt = 0; nt < 8; nt++)
#pragma unroll
        for (int i = 0; i < 4; i++) co[nt][i] = 0.f;
    float m0 = -1e30f, m1 = -1e30f, l0 = 0.f, l1 = 0.f;
    const int c0 = (lane & 3) * 2;

    for (int kt = 0; kt < LL / 64; kt++) {
        const int st = kt & 1;
        __syncthreads();                       // prior compute done before overwrite
        if (kt + 1 < LL / 64) {
            load_kv(kt + 1, st ^ 1);
            cp_wait<1>();
        } else {
            cp_wait<0>();
        }
        __syncthreads();

        const uint32_t sK = sK0 + st * 64 * ATS * 2;
        const uint32_t sV = sV0 + st * 64 * ATS * 2;

        // ---- S = Q K^T ----
        float cs[8][4];
#pragma unroll
        for (int nt = 0; nt < 8; nt++)
#pragma unroll
            for (int i = 0; i < 4; i++) cs[nt][i] = 0.f;
#pragma unroll
        for (int kc = 0; kc < 4; kc++) {
            uint32_t bk[4][4];
#pragma unroll
            for (int np = 0; np < 4; np++) {
                uint32_t addr = sK + (((np * 16 + (lane & 7) + ((lane >> 4) << 3)) * ATS)
                                      + kc * 16 + (((lane >> 3) & 1) << 3)) * 2;
                ldm_x4(bk[np], addr);
            }
#pragma unroll
            for (int nt = 0; nt < 8; nt++)
                mma16816(cs[nt], aq[kc], bk[nt >> 1] + (nt & 1) * 2);
        }

        // ---- online softmax ----
        float sv[8][4];
        float mx0 = -1e30f, mx1 = -1e30f;
#pragma unroll
        for (int nt = 0; nt < 8; nt++) {
            float a0 = MD[st][nt * 8 + c0], a1 = MD[st][nt * 8 + c0 + 1];
            sv[nt][0] = cs[nt][0] * scl + a0;
            sv[nt][1] = cs[nt][1] * scl + a1;
            sv[nt][2] = cs[nt][2] * scl + a0;
            sv[nt][3] = cs[nt][3] * scl + a1;
            mx0 = fmaxf(mx0, fmaxf(sv[nt][0], sv[nt][1]));
            mx1 = fmaxf(mx1, fmaxf(sv[nt][2], sv[nt][3]));
        }
        mx0 = fmaxf(mx0, __shfl_xor_sync(0xffffffffu, mx0, 1));
        mx0 = fmaxf(mx0, __shfl_xor_sync(0xffffffffu, mx0, 2));
        mx1 = fmaxf(mx1, __shfl_xor_sync(0xffffffffu, mx1, 1));
        mx1 = fmaxf(mx1, __shfl_xor_sync(0xffffffffu, mx1, 2));
        float mn0 = fmaxf(m0, mx0), mn1 = fmaxf(m1, mx1);
        float cr0 = __expf(m0 - mn0), cr1 = __expf(m1 - mn1);
        l0 *= cr0; l1 *= cr1;
#pragma unroll
        for (int nt = 0; nt < 8; nt++) {
            co[nt][0] *= cr0; co[nt][1] *= cr0;
            co[nt][2] *= cr1; co[nt][3] *= cr1;
        }
        float ps0 = 0.f, ps1 = 0.f;
        uint32_t ph[8][2];
#pragma unroll
        for (int nt = 0; nt < 8; nt++) {
            float p0 = __expf(sv[nt][0] - mn0);
            float p1 = __expf(sv[nt][1] - mn0);
            float p2 = __expf(sv[nt][2] - mn1);
            float p3 = __expf(sv[nt][3] - mn1);
            ps0 += p0 + p1; ps1 += p2 + p3;
            ph[nt][0] = packh2(p0, p1);
            ph[nt][1] = packh2(p2, p3);
        }
        ps0 += __shfl_xor_sync(0xffffffffu, ps0, 1);
        ps0 += __shfl_xor_sync(0xffffffffu, ps0, 2);
        ps1 += __shfl_xor_sync(0xffffffffu, ps1, 1);
        ps1 += __shfl_xor_sync(0xffffffffu, ps1, 2);
        l0 += ps0; l1 += ps1;
        m0 = mn0; m1 = mn1;

        // ---- O += P V ----
#pragma unroll
        for (int kc = 0; kc < 4; kc++) {
            uint32_t bv[4][4];
#pragma unroll
            for (int np = 0; np < 4; np++) {
                uint32_t addr = sV + (((kc * 16 + (lane & 7) + (((lane >> 3) & 1) << 3)) * ATS)
                                      + np * 16 + ((lane >> 4) << 3)) * 2;
                ldm_x4_t(bv[np], addr);
            }
            uint32_t a[4] = { ph[2 * kc][0], ph[2 * kc][1], ph[2 * kc + 1][0], ph[2 * kc + 1][1] };
#pragma unroll
            for (int nt = 0; nt < 8; nt++)
                mma16816(co[nt], a, bv[nt >> 1] + (nt & 1) * 2);
        }
    }

    float inv0 = 1.f / l0, inv1 = 1.f / l1;
    __half* ob = out + ((size_t)(b * LL + q0 + mwb)) * DD + h * HDIM;
    const int r0 = lane >> 2;
#pragma unroll
    for (int nt = 0; nt < 8; nt++) {
        int col = nt * 8 + c0;
        *(__half2*)(ob + (size_t)r0 * DD + col)       = __floats2half2_rn(co[nt][0] * inv0, co[nt][1] * inv0);
        *(__half2*)(ob + (size_t)(r0 + 8) * DD + col) = __floats2half2_rn(co[nt][2] * inv1, co[nt][3] * inv1);
    }
}

// ---------------- fused residual + mask + LayerNorm (fp32 + fp16 outputs) ----------------
__global__ void add_mask_ln_kernel(const float* __restrict__ y, const float* __restrict__ xin,
                                   const float* __restrict__ qmask,
                                   const float* __restrict__ gam, const float* __restrict__ bet,
                                   float* __restrict__ xout, __half* __restrict__ xouth) {
    __shared__ float red[4];
    const int row = blockIdx.x;
    const int tid = threadIdx.x;
    const float qmv = qmask[row];
    const float* yr = y + (size_t)row * DD;
    const float* xr = xin + (size_t)row * DD;

    float vals[4];
    float s = 0.f;
#pragma unroll
    for (int i = 0; i < 4; i++) {
        int idx = tid + i * 128;
        vals[i] = yr[idx] * qmv + xr[idx];
        s += vals[i];
    }
#pragma unroll
    for (int off = 16; off > 0; off >>= 1) s += __shfl_down_sync(0xffffffffu, s, off);
    if ((tid & 31) == 0) red[tid >> 5] = s;
    __syncthreads();
    float mean = (red[0] + red[1] + red[2] + red[3]) * (1.f / DD);

    float s2 = 0.f;
#pragma unroll
    for (int i = 0; i < 4; i++) {
        float d = vals[i] - mean;
        s2 += d * d;
    }
    __syncthreads();
#pragma unroll
    for (int off = 16; off > 0; off >>= 1) s2 += __shfl_down_sync(0xffffffffu, s2, off);
    if ((tid & 31) == 0) red[tid >> 5] = s2;
    __syncthreads();
    float var = (red[0] + red[1] + red[2] + red[3]) * (1.f / DD);
    float inv = rsqrtf(var + 1e-5f);

    float* xo = xout + (size_t)row * DD;
    __half* xoh = xouth + (size_t)row * DD;
#pragma unroll
    for (int i = 0; i < 4; i++) {
        int idx = tid + i * 128;
        float r = (vals[i] - mean) * inv * gam[idx] + bet[idx];
        xo[idx] = r;
        xoh[idx] = __float2half(r);
    }
}

// ---------------- launch ----------------
extern "C" void kernel_launch(void* const* d_in, const int* in_sizes, int n_in,
                              void* d_out, int out_size) {
    const float* query = (const float*)d_in[0];
    const float* key   = (const float*)d_in[1];
    const float* qmask = (const float*)d_in[2];
    const float* kmask = (const float*)d_in[3];
    const float* bq = (const float*)d_in[5];
    const float* bk = (const float*)d_in[7];
    const float* bv = (const float*)d_in[9];
    const float* bo = (const float*)d_in[11];
    const float* b1 = (const float*)d_in[13];
    const float* b2 = (const float*)d_in[15];
    const float* ln1g = (const float*)d_in[16];
    const float* ln1b = (const float*)d_in[17];
    const float* ln2g = (const float*)d_in[18];
    const float* ln2b = (const float*)d_in[19];
    float* out = (float*)d_out;

    float *px, *pt;
    __half *pqh, *pkvh, *pxh, *pkh, *pah, *phh;
    __half *wq, *wk, *wv, *wo, *w1, *w2;
    cudaGetSymbolAddress((void**)&px, g_x);
    cudaGetSymbolAddress((void**)&pt, g_t);
    cudaGetSymbolAddress((void**)&pqh, g_qh);
    cudaGetSymbolAddress((void**)&pkvh, g_kvh);
    cudaGetSymbolAddress((void**)&pxh, g_xh);
    cudaGetSymbolAddress((void**)&pkh, g_kh);
    cudaGetSymbolAddress((void**)&pah, g_ah);
    cudaGetSymbolAddress((void**)&phh, g_hh);
    cudaGetSymbolAddress((void**)&wq, g_wqh);
    cudaGetSymbolAddress((void**)&wk, g_wkh);
    cudaGetSymbolAddress((void**)&wv, g_wvh);
    cudaGetSymbolAddress((void**)&wo, g_woh);
    cudaGetSymbolAddress((void**)&w1, g_w1h);
    cudaGetSymbolAddress((void**)&w2, g_w2h);

    __half* pkp = pkvh;                 // K projection
    __half* pvp = pkvh + (size_t)ROWS * DD;  // V projection

    // weight + input conversions
    {
        int nD = NLAYERS * DD * DD / 4;
        int nF = NLAYERS * FF * DD / 4;
        f2h_kernel<<<(nD + 255) / 256, 256>>>((const float*)d_in[4],  wq, nD);
        f2h_kernel<<<(nD + 255) / 256, 256>>>((const float*)d_in[6],  wk, nD);
        f2h_kernel<<<(nD + 255) / 256, 256>>>((const float*)d_in[8],  wv, nD);
        f2h_kernel<<<(nD + 255) / 256, 256>>>((const float*)d_in[10], wo, nD);
        f2h_kernel<<<(nF + 255) / 256, 256>>>((const float*)d_in[12], w1, nF);
        f2h_kernel<<<(nF + 255) / 256, 256>>>((const float*)d_in[14], w2, nF);
        int nX = ROWS * DD / 4;
        f2h_kernel<<<(nX + 255) / 256, 256>>>(key, pkh, nX);
        copy_both_kernel<<<(nX + 255) / 256, 256>>>(query, px, pxh, nX);
    }

    const dim3 gemm_blk(256);
    const dim3 gD(DD / 128, ROWS / 128);
    const dim3 gF(FF / 128, ROWS / 128);
    const dim3 gAttn(LL / 64, HH, BB);

    for (int li = 0; li < NLAYERS; li++) {
        const size_t wED = (size_t)li * DD * DD;
        const size_t wFD = (size_t)li * FF * DD;

        gemm_tc<false, true><<<gD, gemm_blk>>>(pxh, wq + wED, bq + li * DD, pqh, ROWS, DD, DD);
        gemm_tc<false, true><<<gD, gemm_blk>>>(pkh, wk + wED, bk + li * DD, pkp, ROWS, DD, DD);
        gemm_tc<false, true><<<gD, gemm_blk>>>(pkh, wv + wED, bv + li * DD, pvp, ROWS, DD, DD);

        attn_tc<<<gAttn, 128>>>(pqh, pkp, pvp, kmask, pah);

        gemm_tc<false, false><<<gD, gemm_blk>>>(pah, wo + wED, bo + li * DD, pt, ROWS, DD, DD);
        add_mask_ln_kernel<<<ROWS, 128>>>(pt, px, qmask, ln1g + li * DD, ln1b + li * DD, px, pxh);

        gemm_tc<true, true><<<gF, gemm_blk>>>(pxh, w1 + wFD, b1 + li * FF, phh, ROWS, FF, DD);
        gemm_tc<false, false><<<gD, gemm_blk>>>(phh, w2 + wFD, b2 + li * DD, pt, ROWS, DD, FF);

        float* dst = (li == NLAYERS - 1) ? out : px;
        add_mask_ln_kernel<<<ROWS, 128>>>(pt, px, qmask, ln2g + li * DD, ln2b + li * DD, dst, pxh);
    }
}

// round 9
// speedup vs baseline: 8.0103x; 1.0739x over previous
#include <cuda_runtime.h>
#include <cuda_fp16.h>
#include <cstdint>

#define BB 4
#define LL 1024
#define DD 512
#define HH 8
#define HDIM 64
#define FF 2048
#define NLAYERS 6
#define ROWS (BB*LL)        // 4096
#define KVW (NLAYERS*2*DD)  // 6144

// ---------------- scratch (no allocation allowed) ----------------
__device__ float g_x[ROWS*DD];
__device__ float g_t[ROWS*DD];
__device__ float g_bkv[KVW];
__device__ int   g_kt[4];
__device__ __half g_qh[ROWS*DD];
__device__ __half g_xh[ROWS*DD];
__device__ __half g_kh[ROWS*DD];
__device__ __half g_ah[ROWS*DD];
__device__ __half g_hh[ROWS*FF];
__device__ __half g_kvp[(size_t)ROWS*KVW];     // all-layer K|V projections
__device__ __half g_wqh[NLAYERS*DD*DD];
__device__ __half g_woh[NLAYERS*DD*DD];
__device__ __half g_wkvh[NLAYERS*2*DD*DD];     // interleaved [li][K|V]
__device__ __half g_w1h[NLAYERS*FF*DD];
__device__ __half g_w2h[NLAYERS*FF*DD];

// ---------------- helpers ----------------
__device__ __forceinline__ uint32_t smem_u32(const void* p) {
    uint32_t a;
    asm("{ .reg .u64 t; cvta.to.shared.u64 t, %1; cvt.u32.u64 %0, t; }" : "=r"(a) : "l"(p));
    return a;
}
__device__ __forceinline__ void cp_async16(uint32_t dst, const void* src) {
    asm volatile("cp.async.cg.shared.global [%0], [%1], 16;" :: "r"(dst), "l"(src) : "memory");
}
__device__ __forceinline__ void cp_commit() {
    asm volatile("cp.async.commit_group;" ::: "memory");
}
template<int N>
__device__ __forceinline__ void cp_wait() {
    asm volatile("cp.async.wait_group %0;" :: "n"(N) : "memory");
}
__device__ __forceinline__ void ldm_x4(uint32_t* r, uint32_t addr) {
    asm volatile("ldmatrix.sync.aligned.m8n8.x4.shared.b16 {%0,%1,%2,%3}, [%4];"
                 : "=r"(r[0]), "=r"(r[1]), "=r"(r[2]), "=r"(r[3]) : "r"(addr));
}
__device__ __forceinline__ void ldm_x4_t(uint32_t* r, uint32_t addr) {
    asm volatile("ldmatrix.sync.aligned.m8n8.x4.trans.shared.b16 {%0,%1,%2,%3}, [%4];"
                 : "=r"(r[0]), "=r"(r[1]), "=r"(r[2]), "=r"(r[3]) : "r"(addr));
}
__device__ __forceinline__ void mma16816(float* c, const uint32_t* a, const uint32_t* b) {
    asm volatile(
        "mma.sync.aligned.m16n8k16.row.col.f32.f16.f16.f32 "
        "{%0,%1,%2,%3}, {%4,%5,%6,%7}, {%8,%9}, {%0,%1,%2,%3};"
        : "+f"(c[0]), "+f"(c[1]), "+f"(c[2]), "+f"(c[3])
        : "r"(a[0]), "r"(a[1]), "r"(a[2]), "r"(a[3]), "r"(b[0]), "r"(b[1]));
}
__device__ __forceinline__ uint32_t packh2(float a, float b) {
    __half2 h = __floats2half2_rn(a, b);
    return *(uint32_t*)&h;
}

// ---------------- startup conversion kernels ----------------
// wq | wo | w1 | w2 | key  -> fp16, one kernel
#define CVT_WQ 393216
#define CVT_WO (CVT_WQ + 393216)
#define CVT_W1 (CVT_WO + 1572864)
#define CVT_W2 (CVT_W1 + 1572864)
#define CVT_KEY (CVT_W2 + 524288)

__global__ void convert_all(const float* __restrict__ wq, const float* __restrict__ wo,
                            const float* __restrict__ w1, const float* __restrict__ w2,
                            const float* __restrict__ key,
                            __half* dwq, __half* dwo, __half* dw1, __half* dw2, __half* dkey) {
    int i = blockIdx.x * blockDim.x + threadIdx.x;
    const float* s; __half* d; int off;
    if (i < CVT_WQ)       { s = wq;  d = dwq;  off = i; }
    else if (i < CVT_WO)  { s = wo;  d = dwo;  off = i - CVT_WQ; }
    else if (i < CVT_W1)  { s = w1;  d = dw1;  off = i - CVT_WO; }
    else if (i < CVT_W2)  { s = w2;  d = dw2;  off = i - CVT_W1; }
    else if (i < CVT_KEY) { s = key; d = dkey; off = i - CVT_W2; }
    else return;
    float4 v = ((const float4*)s)[off];
    __half2* d2 = (__half2*)d + (size_t)off * 2;
    d2[0] = __floats2half2_rn(v.x, v.y);
    d2[1] = __floats2half2_rn(v.z, v.w);
}

// Wk/Wv interleave: dst layer block = [K rows (512) | V rows (512)]
__global__ void wkv_f2h(const float* __restrict__ wk, const float* __restrict__ wv,
                        __half* __restrict__ dst) {
    int i = blockIdx.x * blockDim.x + threadIdx.x;   // 0 .. 6*131072-1 (float4 units)
    if (i >= NLAYERS * 131072) return;
    int li = i / 131072, rem = i % 131072;
    const float4* src = (rem < 65536)
        ? ((const float4*)wk + (size_t)li * 65536 + rem)
        : ((const float4*)wv + (size_t)li * 65536 + (rem - 65536));
    float4 v = *src;
    __half2* d2 = (__half2*)dst + ((size_t)li * 131072 + rem) * 2;
    d2[0] = __floats2half2_rn(v.x, v.y);
    d2[1] = __floats2half2_rn(v.z, v.w);
}

__global__ void biaspack_kernel(const float* __restrict__ bk, const float* __restrict__ bv,
                                float* __restrict__ dst) {
    int i = blockIdx.x * blockDim.x + threadIdx.x;
    if (i < KVW) {
        int li = i >> 10, r = i & 1023;
        dst[i] = (r < 512) ? bk[li * 512 + r] : bv[li * 512 + (r - 512)];
    }
}

__global__ void ktiles_kernel(const float* __restrict__ kmask, int* __restrict__ kt) {
    __shared__ float red[8];
    int b = blockIdx.x;
    int tid = threadIdx.x;
    float s = 0.f;
    for (int i = tid; i < LL; i += 256) s += kmask[b * LL + i];
#pragma unroll
    for (int o = 16; o > 0; o >>= 1) s += __shfl_down_sync(0xffffffffu, s, o);
    if ((tid & 31) == 0) red[tid >> 5] = s;
    __syncthreads();
    if (tid == 0) {
        float t = 0.f;
        for (int i = 0; i < 8; i++) t += red[i];
        kt[b] = ((int)(t + 0.5f) + 63) >> 6;
    }
}

__global__ void copy_both_kernel(const float* __restrict__ s, float* __restrict__ d,
                                 __half* __restrict__ dh, int n4) {
    int i = blockIdx.x * blockDim.x + threadIdx.x;
    if (i < n4) {
        float4 v = ((const float4*)s)[i];
        ((float4*)d)[i] = v;
        __half2* d2 = (__half2*)dh + (size_t)i * 2;
        d2[0] = __floats2half2_rn(v.x, v.y);
        d2[1] = __floats2half2_rn(v.z, v.w);
    }
}

// ---------------- HMMA fp16 GEMM: C[M,N] = A[M,K] @ W[N,K]^T + bias ----------------
// optional ReLU, fp16 out, or fused (y*qm + xres) residual epilogue (fp32 out)
#define GSTR 40
#define STAGE_HALFS (128 * GSTR * 2)

template<bool RELU, bool OUTH, bool ADDRES>
__global__ __launch_bounds__(256)
void gemm_tc(const __half* __restrict__ A, const __half* __restrict__ Wt,
             const float* __restrict__ bias, void* __restrict__ Cout,
             int M, int N, int K,
             const float* __restrict__ xres, const float* __restrict__ qmask) {
    __shared__ __half sh[2 * STAGE_HALFS];
    const uint32_t sb = smem_u32(sh);
    const int tid = threadIdx.x;
    const int wid = tid >> 5;
    const int lane = tid & 31;
    const int m0 = blockIdx.y * 128;
    const int n0 = blockIdx.x * 128;

    const int mwb = (wid >> 1) * 32;
    const int nwb = (wid & 1) * 64;

    float c[2][8][4];
#pragma unroll
    for (int mt = 0; mt < 2; mt++)
#pragma unroll
        for (int nt = 0; nt < 8; nt++)
#pragma unroll
            for (int i = 0; i < 4; i++) c[mt][nt][i] = 0.f;

    const int nch = K >> 5;

    auto load_stage = [&](int kc, int stage) {
        const uint32_t sbase = sb + stage * STAGE_HALFS * 2;
#pragma unroll
        for (int it = 0; it < 4; it++) {
            int idx = tid + it * 256;
            int r = (idx & 511) >> 2;
            int cseg = idx & 3;
            const __half* src;
            uint32_t dst;
            if (idx < 512) {
                src = A + (size_t)(m0 + r) * K + kc * 32 + cseg * 8;
                dst = sbase + (r * GSTR + cseg * 8) * 2;
            } else {
                src = Wt + (size_t)(n0 + r) * K + kc * 32 + cseg * 8;
                dst = sbase + (128 * GSTR + r * GSTR + cseg * 8) * 2;
            }
            cp_async16(dst, src);
        }
        cp_commit();
    };

    load_stage(0, 0);

    for (int kc = 0; kc < nch; kc++) {
        const int stage = kc & 1;
        if (kc + 1 < nch) {
            load_stage(kc + 1, stage ^ 1);
            cp_wait<1>();
        } else {
            cp_wait<0>();
        }
        __syncthreads();

        const uint32_t Ab = sb + stage * STAGE_HALFS * 2;
        const uint32_t Bb = Ab + 128 * GSTR * 2;

#pragma unroll
        for (int ks = 0; ks < 2; ks++) {
            uint32_t afr[2][4], bfr[4][4];
#pragma unroll
            for (int mt = 0; mt < 2; mt++) {
                uint32_t addr = Ab + (((mwb + mt * 16 + (lane & 15)) * GSTR)
                                      + ks * 16 + ((lane >> 4) << 3)) * 2;
                ldm_x4(afr[mt], addr);
            }
#pragma unroll
            for (int np = 0; np < 4; np++) {
                uint32_t addr = Bb + (((nwb + np * 16 + (lane & 7) + ((lane >> 4) << 3)) * GSTR)
                                      + ks * 16 + (((lane >> 3) & 1) << 3)) * 2;
                ldm_x4(bfr[np], addr);
            }
#pragma unroll
            for (int mt = 0; mt < 2; mt++)
#pragma unroll
                for (int nt = 0; nt < 8; nt++)
                    mma16816(c[mt][nt], afr[mt], bfr[nt >> 1] + (nt & 1) * 2);
        }
        __syncthreads();
    }

#pragma unroll
    for (int mt = 0; mt < 2; mt++) {
        const int r0 = m0 + mwb + mt * 16 + (lane >> 2);
        float qm0 = 0.f, qm1 = 0.f;
        if (ADDRES) { qm0 = qmask[r0]; qm1 = qmask[r0 + 8]; }
#pragma unroll
        for (int nt = 0; nt < 8; nt++) {
            int col = n0 + nwb + nt * 8 + (lane & 3) * 2;
            float bv0 = bias[col], bv1 = bias[col + 1];
            float v0 = c[mt][nt][0] + bv0;
            float v1 = c[mt][nt][1] + bv1;
            float v2 = c[mt][nt][2] + bv0;
            float v3 = c[mt][nt][3] + bv1;
            if (RELU) {
                v0 = fmaxf(v0, 0.f); v1 = fmaxf(v1, 0.f);
                v2 = fmaxf(v2, 0.f); v3 = fmaxf(v3, 0.f);
            }
            if (ADDRES) {
                float2 x0 = *(const float2*)(xres + (size_t)r0 * N + col);
                float2 x1 = *(const float2*)(xres + (size_t)(r0 + 8) * N + col);
                v0 = v0 * qm0 + x0.x; v1 = v1 * qm0 + x0.y;
                v2 = v2 * qm1 + x1.x; v3 = v3 * qm1 + x1.y;
            }
            if (OUTH) {
                __half* base = (__half*)Cout;
                *(__half2*)(base + (size_t)r0 * N + col)       = __floats2half2_rn(v0, v1);
                *(__half2*)(base + (size_t)(r0 + 8) * N + col) = __floats2half2_rn(v2, v3);
            } else {
                float* base = (float*)Cout;
                *(float2*)(base + (size_t)r0 * N + col)       = make_float2(v0, v1);
                *(float2*)(base + (size_t)(r0 + 8) * N + col) = make_float2(v2, v3);
            }
        }
    }
}

// ---------------- HMMA flash attention (dynamic valid-tile count) ----------------
#define ATS 72

__global__ __launch_bounds__(128)
void attn_tc(const __half* __restrict__ q, const __half* __restrict__ kb0,
             const __half* __restrict__ vb0, int kvs,
             const int* __restrict__ ktarr, const float* __restrict__ kmask,
             __half* __restrict__ out) {
    __shared__ __half Qs[64 * ATS];
    __shared__ __half Ks[2][64 * ATS];
    __shared__ __half Vs[2][64 * ATS];
    __shared__ float MD[2][64];

    const int q0 = blockIdx.x * 64;
    const int h  = blockIdx.y;
    const int b  = blockIdx.z;
    const int tid = threadIdx.x;
    const int wid = tid >> 5;
    const int lane = tid & 31;
    const int mwb = wid * 16;
    const float scl = 0.125f;
    const int NT = ktarr[b];

    const uint32_t sQ = smem_u32(Qs);
    const uint32_t sK0 = smem_u32(Ks);
    const uint32_t sV0 = smem_u32(Vs);

    const __half* qb = q + ((size_t)(b * LL + q0)) * DD + h * HDIM;
#pragma unroll
    for (int i = 0; i < 4; i++) {
        int idx = tid + i * 128;
        int r = idx >> 3, c8 = (idx & 7) * 8;
        cp_async16(sQ + (r * ATS + c8) * 2, qb + (size_t)r * DD + c8);
    }
    cp_commit();

    auto load_kv = [&](int kt, int st) {
        const int k0 = kt * 64;
        const __half* kb = kb0 + ((size_t)(b * LL + k0)) * kvs + h * HDIM;
        const __half* vb = vb0 + ((size_t)(b * LL + k0)) * kvs + h * HDIM;
        const uint32_t sK = sK0 + st * 64 * ATS * 2;
        const uint32_t sV = sV0 + st * 64 * ATS * 2;
#pragma unroll
        for (int i = 0; i < 8; i++) {
            int idx = tid + i * 128;
            int r = (idx & 511) >> 3, c8 = (idx & 7) * 8;
            if (idx < 512) cp_async16(sK + (r * ATS + c8) * 2, kb + (size_t)r * kvs + c8);
            else           cp_async16(sV + (r * ATS + c8) * 2, vb + (size_t)r * kvs + c8);
        }
        if (tid < 64) MD[st][tid] = (kmask[b * LL + k0 + tid] == 0.f) ? -1e30f : 0.f;
        cp_commit();
    };

    load_kv(0, 0);
    cp_wait<1>();
    __syncthreads();

    uint32_t aq[4][4];
#pragma unroll
    for (int kc = 0; kc < 4; kc++) {
        uint32_t addr = sQ + (((mwb + (lane & 15)) * ATS) + kc * 16 + ((lane >> 4) << 3)) * 2;
        ldm_x4(aq[kc], addr);
    }

    float co[8][4];
#pragma unroll
    for (int nt = 0; nt < 8; nt++)
#pragma unroll
        for (int i = 0; i < 4; i++) co[nt][i] = 0.f;
    float m0 = -1e30f, m1 = -1e30f, l0 = 0.f, l1 = 0.f;
    const int c0 = (lane & 3) * 2;

    for (int kt = 0; kt < NT; kt++) {
        const int st = kt & 1;
        __syncthreads();
        if (kt + 1 < NT) {
            load_kv(kt + 1, st ^ 1);
            cp_wait<1>();
        } else {
            cp_wait<0>();
        }
        __syncthreads();

        const uint32_t sK = sK0 + st * 64 * ATS * 2;
        const uint32_t sV = sV0 + st * 64 * ATS * 2;

        // ---- S = Q K^T ----
        float cs[8][4];
#pragma unroll
        for (int nt = 0; nt < 8; nt++)
#pragma unroll
            for (int i = 0; i < 4; i++) cs[nt][i] = 0.f;
#pragma unroll
        for (int kc = 0; kc < 4; kc++) {
            uint32_t bk[4][4];
#pragma unroll
            for (int np = 0; np < 4; np++) {
                uint32_t addr = sK + (((np * 16 + (lane & 7) + ((lane >> 4) << 3)) * ATS)
                                      + kc * 16 + (((lane >> 3) & 1) << 3)) * 2;
                ldm_x4(bk[np], addr);
            }
#pragma unroll
            for (int nt = 0; nt < 8; nt++)
                mma16816(cs[nt], aq[kc], bk[nt >> 1] + (nt & 1) * 2);
        }

        // ---- online softmax ----
        float sv[8][4];
        float mx0 = -1e30f, mx1 = -1e30f;
#pragma unroll
        for (int nt = 0; nt < 8; nt++) {
            float a0 = MD[st][nt * 8 + c0], a1 = MD[st][nt * 8 + c0 + 1];
            sv[nt][0] = cs[nt][0] * scl + a0;
            sv[nt][1] = cs[nt][1] * scl + a1;
            sv[nt][2] = cs[nt][2] * scl + a0;
            sv[nt][3] = cs[nt][3] * scl + a1;
            mx0 = fmaxf(mx0, fmaxf(sv[nt][0], sv[nt][1]));
            mx1 = fmaxf(mx1, fmaxf(sv[nt][2], sv[nt][3]));
        }
        mx0 = fmaxf(mx0, __shfl_xor_sync(0xffffffffu, mx0, 1));
        mx0 = fmaxf(mx0, __shfl_xor_sync(0xffffffffu, mx0, 2));
        mx1 = fmaxf(mx1, __shfl_xor_sync(0xffffffffu, mx1, 1));
        mx1 = fmaxf(mx1, __shfl_xor_sync(0xffffffffu, mx1, 2));
        float mn0 = fmaxf(m0, mx0), mn1 = fmaxf(m1, mx1);
        float cr0 = __expf(m0 - mn0), cr1 = __expf(m1 - mn1);
        l0 *= cr0; l1 *= cr1;
#pragma unroll
        for (int nt = 0; nt < 8; nt++) {
            co[nt][0] *= cr0; co[nt][1] *= cr0;
            co[nt][2] *= cr1; co[nt][3] *= cr1;
        }
        float ps0 = 0.f, ps1 = 0.f;
        uint32_t ph[8][2];
#pragma unroll
        for (int nt = 0; nt < 8; nt++) {
            float p0 = __expf(sv[nt][0] - mn0);
            float p1 = __expf(sv[nt][1] - mn0);
            float p2 = __expf(sv[nt][2] - mn1);
            float p3 = __expf(sv[nt][3] - mn1);
            ps0 += p0 + p1; ps1 += p2 + p3;
            ph[nt][0] = packh2(p0, p1);
            ph[nt][1] = packh2(p2, p3);
        }
        ps0 += __shfl_xor_sync(0xffffffffu, ps0, 1);
        ps0 += __shfl_xor_sync(0xffffffffu, ps0, 2);
        ps1 += __shfl_xor_sync(0xffffffffu, ps1, 1);
        ps1 += __shfl_xor_sync(0xffffffffu, ps1, 2);
        l0 += ps0; l1 += ps1;
        m0 = mn0; m1 = mn1;

        // ---- O += P V ----
#pragma unroll
        for (int kc = 0; kc < 4; kc++) {
            uint32_t bv[4][4];
#pragma unroll
            for (int np = 0; np < 4; np++) {
                uint32_t addr = sV + (((kc * 16 + (lane & 7) + (((lane >> 3) & 1) << 3)) * ATS)
                                      + np * 16 + ((lane >> 4) << 3)) * 2;
                ldm_x4_t(bv[np], addr);
            }
            uint32_t a[4] = { ph[2 * kc][0], ph[2 * kc][1], ph[2 * kc + 1][0], ph[2 * kc + 1][1] };
#pragma unroll
            for (int nt = 0; nt < 8; nt++)
                mma16816(co[nt], a, bv[nt >> 1] + (nt & 1) * 2);
        }
    }

    float inv0 = 1.f / l0, inv1 = 1.f / l1;
    __half* ob = out + ((size_t)(b * LL + q0 + mwb)) * DD + h * HDIM;
    const int r0 = lane >> 2;
#pragma unroll
    for (int nt = 0; nt < 8; nt++) {
        int col = nt * 8 + c0;
        *(__half2*)(ob + (size_t)r0 * DD + col)       = __floats2half2_rn(co[nt][0] * inv0, co[nt][1] * inv0);
        *(__half2*)(ob + (size_t)(r0 + 8) * DD + col) = __floats2half2_rn(co[nt][2] * inv1, co[nt][3] * inv1);
    }
}

// ---------------- LayerNorm (input already has residual+mask applied) ----------------
__global__ void ln_kernel(const float* __restrict__ y,
                          const float* __restrict__ gam, const float* __restrict__ bet,
                          float* __restrict__ xout, __half* __restrict__ xouth) {
    __shared__ float red[4];
    const int row = blockIdx.x;
    const int tid = threadIdx.x;
    const float* yr = y + (size_t)row * DD;

    float vals[4];
    float s = 0.f;
#pragma unroll
    for (int i = 0; i < 4; i++) {
        int idx = tid + i * 128;
        vals[i] = yr[idx];
        s += vals[i];
    }
#pragma unroll
    for (int off = 16; off > 0; off >>= 1) s += __shfl_down_sync(0xffffffffu, s, off);
    if ((tid & 31) == 0) red[tid >> 5] = s;
    __syncthreads();
    float mean = (red[0] + red[1] + red[2] + red[3]) * (1.f / DD);

    float s2 = 0.f;
#pragma unroll
    for (int i = 0; i < 4; i++) {
        float d = vals[i] - mean;
        s2 += d * d;
    }
    __syncthreads();
#pragma unroll
    for (int off = 16; off > 0; off >>= 1) s2 += __shfl_down_sync(0xffffffffu, s2, off);
    if ((tid & 31) == 0) red[tid >> 5] = s2;
    __syncthreads();
    float var = (red[0] + red[1] + red[2] + red[3]) * (1.f / DD);
    float inv = rsqrtf(var + 1e-5f);

    float* xo = xout + (size_t)row * DD;
    __half* xoh = xouth + (size_t)row * DD;
#pragma unroll
    for (int i = 0; i < 4; i++) {
        int idx = tid + i * 128;
        float r = (vals[i] - mean) * inv * gam[idx] + bet[idx];
        xo[idx] = r;
        xoh[idx] = __float2half(r);
    }
}

// ---------------- launch ----------------
extern "C" void kernel_launch(void* const* d_in, const int* in_sizes, int n_in,
                              void* d_out, int out_size) {
    const float* query = (const float*)d_in[0];
    const float* key   = (const float*)d_in[1];
    const float* qmask = (const float*)d_in[2];
    const float* kmask = (const float*)d_in[3];
    const float* bq = (const float*)d_in[5];
    const float* bk = (const float*)d_in[7];
    const float* bv = (const float*)d_in[9];
    const float* bo = (const float*)d_in[11];
    const float* b1 = (const float*)d_in[13];
    const float* b2 = (const float*)d_in[15];
    const float* ln1g = (const float*)d_in[16];
    const float* ln1b = (const float*)d_in[17];
    const float* ln2g = (const float*)d_in[18];
    const float* ln2b = (const float*)d_in[19];
    float* out = (float*)d_out;

    float *px, *pt, *pbkv;
    int* pkt;
    __half *pqh, *pxh, *pkh, *pah, *phh, *pkv;
    __half *wq, *wo, *wkv, *w1, *w2;
    cudaGetSymbolAddress((void**)&px, g_x);
    cudaGetSymbolAddress((void**)&pt, g_t);
    cudaGetSymbolAddress((void**)&pbkv, g_bkv);
    cudaGetSymbolAddress((void**)&pkt, g_kt);
    cudaGetSymbolAddress((void**)&pqh, g_qh);
    cudaGetSymbolAddress((void**)&pxh, g_xh);
    cudaGetSymbolAddress((void**)&pkh, g_kh);
    cudaGetSymbolAddress((void**)&pah, g_ah);
    cudaGetSymbolAddress((void**)&phh, g_hh);
    cudaGetSymbolAddress((void**)&pkv, g_kvp);
    cudaGetSymbolAddress((void**)&wq, g_wqh);
    cudaGetSymbolAddress((void**)&wo, g_woh);
    cudaGetSymbolAddress((void**)&wkv, g_wkvh);
    cudaGetSymbolAddress((void**)&w1, g_w1h);
    cudaGetSymbolAddress((void**)&w2, g_w2h);

    // ---- startup: conversions, bias pack, tile counts, all-layer KV projection ----
    convert_all<<<(CVT_KEY + 255) / 256, 256>>>(
        (const float*)d_in[4], (const float*)d_in[10], (const float*)d_in[12],
        (const float*)d_in[14], key, wq, wo, w1, w2, pkh);
    wkv_f2h<<<(NLAYERS * 131072 + 255) / 256, 256>>>((const float*)d_in[6], (const float*)d_in[8], wkv);
    copy_both_kernel<<<(ROWS * DD / 4 + 255) / 256, 256>>>(query, px, pxh, ROWS * DD / 4);
    biaspack_kernel<<<(KVW + 255) / 256, 256>>>(bk, bv, pbkv);
    ktiles_kernel<<<4, 256>>>(kmask, pkt);

    const dim3 gemm_blk(256);
    const dim3 gD(DD / 128, ROWS / 128);
    const dim3 gF(FF / 128, ROWS / 128);
    const dim3 gKV(KVW / 128, ROWS / 128);   // 48 x 32
    const dim3 gAttn(LL / 64, HH, BB);

    gemm_tc<false, true, false><<<gKV, gemm_blk>>>(pkh, wkv, pbkv, pkv, ROWS, KVW, DD, nullptr, nullptr);

    for (int li = 0; li < NLAYERS; li++) {
        const size_t wED = (size_t)li * DD * DD;
        const size_t wFD = (size_t)li * FF * DD;

        gemm_tc<false, true, false><<<gD, gemm_blk>>>(pxh, wq + wED, bq + li * DD, pqh, ROWS, DD, DD, nullptr, nullptr);

        attn_tc<<<gAttn, 128>>>(pqh, pkv + li * 2 * DD, pkv + li * 2 * DD + DD, KVW, pkt, kmask, pah);

        gemm_tc<false, false, true><<<gD, gemm_blk>>>(pah, wo + wED, bo + li * DD, pt, ROWS, DD, DD, px, qmask);
        ln_kernel<<<ROWS, 128>>>(pt, ln1g + li * DD, ln1b + li * DD, px, pxh);

        gemm_tc<true, true, false><<<gF, gemm_blk>>>(pxh, w1 + wFD, b1 + li * FF, phh, ROWS, FF, DD, nullptr, nullptr);
        gemm_tc<false, false, true><<<gD, gemm_blk>>>(phh, w2 + wFD, b2 + li * DD, pt, ROWS, DD, FF, px, qmask);

        float* dst = (li == NLAYERS - 1) ? out : px;
        ln_kernel<<<ROWS, 128>>>(pt, ln2g + li * DD, ln2b + li * DD, dst, pxh);
    }
}

// round 14
// speedup vs baseline: 8.3070x; 1.0370x over previous
#include <cuda_runtime.h>
#include <cuda_fp16.h>
#include <cstdint>

#define BB 4
#define LL 1024
#define DD 512
#define HH 8
#define HDIM 64
#define FF 2048
#define NLAYERS 6
#define ROWS (BB*LL)        // 4096
#define KVW (NLAYERS*2*DD)  // 6144

// ---------------- scratch (no allocation allowed) ----------------
__device__ float g_x[ROWS*DD];
__device__ float g_t[ROWS*DD];
__device__ float g_bkv[KVW];
__device__ int   g_kt[4];
__device__ __half g_xh[ROWS*DD];
__device__ __half g_kh[ROWS*DD];
__device__ __half g_ah[ROWS*DD];
__device__ __half g_hh[ROWS*FF];
__device__ __half g_kvp[(size_t)ROWS*KVW];     // all-layer K|V projections
__device__ __half g_wqh[NLAYERS*DD*DD];
__device__ __half g_woh[NLAYERS*DD*DD];
__device__ __half g_wkvh[NLAYERS*2*DD*DD];     // interleaved [li][K|V]
__device__ __half g_w1h[NLAYERS*FF*DD];
__device__ __half g_w2h[NLAYERS*FF*DD];

// ---------------- helpers ----------------
__device__ __forceinline__ uint32_t smem_u32(const void* p) {
    uint32_t a;
    asm("{ .reg .u64 t; cvta.to.shared.u64 t, %1; cvt.u32.u64 %0, t; }" : "=r"(a) : "l"(p));
    return a;
}
__device__ __forceinline__ void cp_async16(uint32_t dst, const void* src) {
    asm volatile("cp.async.cg.shared.global [%0], [%1], 16;" :: "r"(dst), "l"(src) : "memory");
}
__device__ __forceinline__ void cp_commit() {
    asm volatile("cp.async.commit_group;" ::: "memory");
}
template<int N>
__device__ __forceinline__ void cp_wait() {
    asm volatile("cp.async.wait_group %0;" :: "n"(N) : "memory");
}
__device__ __forceinline__ void ldm_x4(uint32_t* r, uint32_t addr) {
    asm volatile("ldmatrix.sync.aligned.m8n8.x4.shared.b16 {%0,%1,%2,%3}, [%4];"
                 : "=r"(r[0]), "=r"(r[1]), "=r"(r[2]), "=r"(r[3]) : "r"(addr));
}
__device__ __forceinline__ void ldm_x4_t(uint32_t* r, uint32_t addr) {
    asm volatile("ldmatrix.sync.aligned.m8n8.x4.trans.shared.b16 {%0,%1,%2,%3}, [%4];"
                 : "=r"(r[0]), "=r"(r[1]), "=r"(r[2]), "=r"(r[3]) : "r"(addr));
}
__device__ __forceinline__ void mma16816(float* c, const uint32_t* a, const uint32_t* b) {
    asm volatile(
        "mma.sync.aligned.m16n8k16.row.col.f32.f16.f16.f32 "
        "{%0,%1,%2,%3}, {%4,%5,%6,%7}, {%8,%9}, {%0,%1,%2,%3};"
        : "+f"(c[0]), "+f"(c[1]), "+f"(c[2]), "+f"(c[3])
        : "r"(a[0]), "r"(a[1]), "r"(a[2]), "r"(a[3]), "r"(b[0]), "r"(b[1]));
}
__device__ __forceinline__ uint32_t packh2(float a, float b) {
    __half2 h = __floats2half2_rn(a, b);
    return *(uint32_t*)&h;
}

// ---------------- startup conversion kernels ----------------
#define CVT_WQ 393216
#define CVT_WO (CVT_WQ + 393216)
#define CVT_W1 (CVT_WO + 1572864)
#define CVT_W2 (CVT_W1 + 1572864)
#define CVT_KEY (CVT_W2 + 524288)

__global__ void convert_all(const float* __restrict__ wq, const float* __restrict__ wo,
                            const float* __restrict__ w1, const float* __restrict__ w2,
                            const float* __restrict__ key,
                            __half* dwq, __half* dwo, __half* dw1, __half* dw2, __half* dkey) {
    int i = blockIdx.x * blockDim.x + threadIdx.x;
    const float* s; __half* d; int off;
    if (i < CVT_WQ)       { s = wq;  d = dwq;  off = i; }
    else if (i < CVT_WO)  { s = wo;  d = dwo;  off = i - CVT_WQ; }
    else if (i < CVT_W1)  { s = w1;  d = dw1;  off = i - CVT_WO; }
    else if (i < CVT_W2)  { s = w2;  d = dw2;  off = i - CVT_W1; }
    else if (i < CVT_KEY) { s = key; d = dkey; off = i - CVT_W2; }
    else return;
    float4 v = ((const float4*)s)[off];
    __half2* d2 = (__half2*)d + (size_t)off * 2;
    d2[0] = __floats2half2_rn(v.x, v.y);
    d2[1] = __floats2half2_rn(v.z, v.w);
}

__global__ void wkv_f2h(const float* __restrict__ wk, const float* __restrict__ wv,
                        __half* __restrict__ dst) {
    int i = blockIdx.x * blockDim.x + threadIdx.x;
    if (i >= NLAYERS * 131072) return;
    int li = i / 131072, rem = i % 131072;
    const float4* src = (rem < 65536)
        ? ((const float4*)wk + (size_t)li * 65536 + rem)
        : ((const float4*)wv + (size_t)li * 65536 + (rem - 65536));
    float4 v = *src;
    __half2* d2 = (__half2*)dst + ((size_t)li * 131072 + rem) * 2;
    d2[0] = __floats2half2_rn(v.x, v.y);
    d2[1] = __floats2half2_rn(v.z, v.w);
}

// blocks 0..23: bias pack; blocks 24..27: per-batch valid-key tile count
__global__ void misc_kernel(const float* __restrict__ bk, const float* __restrict__ bv,
                            float* __restrict__ dst,
                            const float* __restrict__ kmask, int* __restrict__ kt) {
    __shared__ float red[8];
    int blk = blockIdx.x;
    int tid = threadIdx.x;
    if (blk < 24) {
        int i = blk * 256 + tid;
        int li = i >> 10, r = i & 1023;
        dst[i] = (r < 512) ? bk[li * 512 + r] : bv[li * 512 + (r - 512)];
    } else {
        int b = blk - 24;
        float s = 0.f;
        for (int i = tid; i < LL; i += 256) s += kmask[b * LL + i];
#pragma unroll
        for (int o = 16; o > 0; o >>= 1) s += __shfl_down_sync(0xffffffffu, s, o);
        if ((tid & 31) == 0) red[tid >> 5] = s;
        __syncthreads();
        if (tid == 0) {
            float t = 0.f;
            for (int i = 0; i < 8; i++) t += red[i];
            kt[b] = ((int)(t + 0.5f) + 63) >> 6;
        }
    }
}

__global__ void copy_both_kernel(const float* __restrict__ s, float* __restrict__ d,
                                 __half* __restrict__ dh, int n4) {
    int i = blockIdx.x * blockDim.x + threadIdx.x;
    if (i < n4) {
        float4 v = ((const float4*)s)[i];
        ((float4*)d)[i] = v;
        __half2* d2 = (__half2*)dh + (size_t)i * 2;
        d2[0] = __floats2half2_rn(v.x, v.y);
        d2[1] = __floats2half2_rn(v.z, v.w);
    }
}

// ---------------- HMMA fp16 GEMM (3-stage cp.async pipeline) ----------------
#define GSTR 40
#define STAGE_HALFS (128 * GSTR * 2)
#define GS3 (3 * STAGE_HALFS * 2)     // 61440 bytes dynamic smem

template<bool RELU, bool OUTH, bool ADDRES>
__global__ __launch_bounds__(256)
void gemm_tc(const __half* __restrict__ A, const __half* __restrict__ Wt,
             const float* __restrict__ bias, void* __restrict__ Cout,
             int M, int N, int K,
             const float* __restrict__ xres, const float* __restrict__ qmask) {
    extern __shared__ char gsm[];
    const uint32_t sb = smem_u32(gsm);
    const int tid = threadIdx.x;
    const int wid = tid >> 5;
    const int lane = tid & 31;
    const int m0 = blockIdx.y * 128;
    const int n0 = blockIdx.x * 128;

    const int mwb = (wid >> 1) * 32;
    const int nwb = (wid & 1) * 64;

    float c[2][8][4];
#pragma unroll
    for (int mt = 0; mt < 2; mt++)
#pragma unroll
        for (int nt = 0; nt < 8; nt++)
#pragma unroll
            for (int i = 0; i < 4; i++) c[mt][nt][i] = 0.f;

    const int nch = K >> 5;

    auto load_stage = [&](int kc, int stage) {
        const uint32_t sbase = sb + stage * STAGE_HALFS * 2;
#pragma unroll
        for (int it = 0; it < 4; it++) {
            int idx = tid + it * 256;
            int r = (idx & 511) >> 2;
            int cseg = idx & 3;
            const __half* src;
            uint32_t dst;
            if (idx < 512) {
                src = A + (size_t)(m0 + r) * K + kc * 32 + cseg * 8;
                dst = sbase + (r * GSTR + cseg * 8) * 2;
            } else {
                src = Wt + (size_t)(n0 + r) * K + kc * 32 + cseg * 8;
                dst = sbase + (128 * GSTR + r * GSTR + cseg * 8) * 2;
            }
            cp_async16(dst, src);
        }
        cp_commit();
    };

    load_stage(0, 0);
    load_stage(1, 1);

    for (int kc = 0; kc < nch; kc++) {
        const int st = kc % 3;
        if (kc + 1 < nch) cp_wait<1>();
        else              cp_wait<0>();
        __syncthreads();
        if (kc + 2 < nch) load_stage(kc + 2, (kc + 2) % 3);

        const uint32_t Ab = sb + st * STAGE_HALFS * 2;
        const uint32_t Bb = Ab + 128 * GSTR * 2;

#pragma unroll
        for (int ks = 0; ks < 2; ks++) {
            uint32_t afr[2][4], bfr[4][4];
#pragma unroll
            for (int mt = 0; mt < 2; mt++) {
                uint32_t addr = Ab + (((mwb + mt * 16 + (lane & 15)) * GSTR)
                                      + ks * 16 + ((lane >> 4) << 3)) * 2;
                ldm_x4(afr[mt], addr);
            }
#pragma unroll
            for (int np = 0; np < 4; np++) {
                uint32_t addr = Bb + (((nwb + np * 16 + (lane & 7) + ((lane >> 4) << 3)) * GSTR)
                                      + ks * 16 + (((lane >> 3) & 1) << 3)) * 2;
                ldm_x4(bfr[np], addr);
            }
#pragma unroll
            for (int mt = 0; mt < 2; mt++)
#pragma unroll
                for (int nt = 0; nt < 8; nt++)
                    mma16816(c[mt][nt], afr[mt], bfr[nt >> 1] + (nt & 1) * 2);
        }
    }

#pragma unroll
    for (int mt = 0; mt < 2; mt++) {
        const int r0 = m0 + mwb + mt * 16 + (lane >> 2);
        float qm0 = 0.f, qm1 = 0.f;
        if (ADDRES) { qm0 = qmask[r0]; qm1 = qmask[r0 + 8]; }
#pragma unroll
        for (int nt = 0; nt < 8; nt++) {
            int col = n0 + nwb + nt * 8 + (lane & 3) * 2;
            float bv0 = bias[col], bv1 = bias[col + 1];
            float v0 = c[mt][nt][0] + bv0;
            float v1 = c[mt][nt][1] + bv1;
            float v2 = c[mt][nt][2] + bv0;
            float v3 = c[mt][nt][3] + bv1;
            if (RELU) {
                v0 = fmaxf(v0, 0.f); v1 = fmaxf(v1, 0.f);
                v2 = fmaxf(v2, 0.f); v3 = fmaxf(v3, 0.f);
            }
            if (ADDRES) {
                float2 x0 = *(const float2*)(xres + (size_t)r0 * N + col);
                float2 x1 = *(const float2*)(xres + (size_t)(r0 + 8) * N + col);
                v0 = v0 * qm0 + x0.x; v1 = v1 * qm0 + x0.y;
                v2 = v2 * qm1 + x1.x; v3 = v3 * qm1 + x1.y;
            }
            if (OUTH) {
                __half* base = (__half*)Cout;
                *(__half2*)(base + (size_t)r0 * N + col)       = __floats2half2_rn(v0, v1);
                *(__half2*)(base + (size_t)(r0 + 8) * N + col) = __floats2half2_rn(v2, v3);
            } else {
                float* base = (float*)Cout;
                *(float2*)(base + (size_t)r0 * N + col)       = make_float2(v0, v1);
                *(float2*)(base + (size_t)(r0 + 8) * N + col) = make_float2(v2, v3);
            }
        }
    }
}

// ---------------- HMMA flash attention with fused Q projection ----------------
// grid (L/64, H, B), 128 threads. Prologue: Q = x @ Wq_head^T + bq (HMMA),
// C-frags repacked directly into A-frags (scale folded). Then flash loop.
#define ATS 72

__global__ __launch_bounds__(128)
void attn_tc(const __half* __restrict__ xh, const __half* __restrict__ wqh,
             const float* __restrict__ bqp,
             const __half* __restrict__ kb0, const __half* __restrict__ vb0, int kvs,
             const int* __restrict__ ktarr, const float* __restrict__ kmask,
             __half* __restrict__ out) {
    __shared__ __half Ks[2][64 * ATS];
    __shared__ __half Vs[2][64 * ATS];
    __shared__ float MD[2][64];

    const int q0 = blockIdx.x * 64;
    const int h  = blockIdx.y;
    const int b  = blockIdx.z;
    const int tid = threadIdx.x;
    const int wid = tid >> 5;
    const int lane = tid & 31;
    const int mwb = wid * 16;
    const float scl = 0.125f;
    const int NT = ktarr[b];

    const uint32_t sK0 = smem_u32(Ks);
    const uint32_t sV0 = smem_u32(Vs);

    // ---- Q projection: Q[64,64] = x[64,512] @ Wq_head[64,512]^T ----
    const __half* xb = xh + ((size_t)(b * LL + q0)) * DD;
    const __half* wb = wqh + (size_t)h * HDIM * DD;

    auto load_qw = [&](int kc, int st) {
        const uint32_t sX = sK0 + st * 64 * ATS * 2;
        const uint32_t sW = sV0 + st * 64 * ATS * 2;
#pragma unroll
        for (int i = 0; i < 4; i++) {
            int idx = tid + i * 128;          // 0..511
            int r = (idx & 255) >> 2, c8 = (idx & 3) * 8;
            if (idx < 256) cp_async16(sX + (r * ATS + c8) * 2, xb + (size_t)r * DD + kc * 32 + c8);
            else           cp_async16(sW + (r * ATS + c8) * 2, wb + (size_t)r * DD + kc * 32 + c8);
        }
        cp_commit();
    };

    float qa[8][4];
#pragma unroll
    for (int nt = 0; nt < 8; nt++)
#pragma unroll
        for (int i = 0; i < 4; i++) qa[nt][i] = 0.f;

    load_qw(0, 0);
    for (int kc = 0; kc < 16; kc++) {
        const int st = kc & 1;
        __syncthreads();
        if (kc + 1 < 16) {
            load_qw(kc + 1, st ^ 1);
            cp_wait<1>();
        } else {
            cp_wait<0>();
        }
        __syncthreads();
        const uint32_t sX = sK0 + st * 64 * ATS * 2;
        const uint32_t sW = sV0 + st * 64 * ATS * 2;
#pragma unroll
        for (int ks = 0; ks < 2; ks++) {
            uint32_t ax[4], bw[4][4];
            {
                uint32_t addr = sX + (((mwb + (lane & 15)) * ATS) + ks * 16 + ((lane >> 4) << 3)) * 2;
                ldm_x4(ax, addr);
            }
#pragma unroll
            for (int np = 0; np < 4; np++) {
                uint32_t addr = sW + (((np * 16 + (lane & 7) + ((lane >> 4) << 3)) * ATS)
                                      + ks * 16 + (((lane >> 3) & 1) << 3)) * 2;
                ldm_x4(bw[np], addr);
            }
#pragma unroll
            for (int nt = 0; nt < 8; nt++)
                mma16816(qa[nt], ax, bw[nt >> 1] + (nt & 1) * 2);
        }
    }

    // bias + scale, repack C-frags as A-frags (C layout == A layout)
    uint32_t aq[4][4];
    {
        const int c0i = (lane & 3) * 2;
#pragma unroll
        for (int nt = 0; nt < 8; nt++) {
            int col = h * HDIM + nt * 8 + c0i;
            float b0 = bqp[col], b1 = bqp[col + 1];
            qa[nt][0] = (qa[nt][0] + b0) * scl;
            qa[nt][1] = (qa[nt][1] + b1) * scl;
            qa[nt][2] = (qa[nt][2] + b0) * scl;
            qa[nt][3] = (qa[nt][3] + b1) * scl;
        }
#pragma unroll
        for (int kc = 0; kc < 4; kc++) {
            aq[kc][0] = packh2(qa[2 * kc][0], qa[2 * kc][1]);
            aq[kc][1] = packh2(qa[2 * kc][2], qa[2 * kc][3]);
            aq[kc][2] = packh2(qa[2 * kc + 1][0], qa[2 * kc + 1][1]);
            aq[kc][3] = packh2(qa[2 * kc + 1][2], qa[2 * kc + 1][3]);
        }
    }
    __syncthreads();     // Q-proj reads done before K/V overwrite

    // ---- flash attention main loop ----
    auto load_kv = [&](int kt, int st) {
        const int k0 = kt * 64;
        const __half* kb = kb0 + ((size_t)(b * LL + k0)) * kvs + h * HDIM;
        const __half* vb = vb0 + ((size_t)(b * LL + k0)) * kvs + h * HDIM;
        const uint32_t sK = sK0 + st * 64 * ATS * 2;
        const uint32_t sV = sV0 + st * 64 * ATS * 2;
#pragma unroll
        for (int i = 0; i < 8; i++) {
            int idx = tid + i * 128;
            int r = (idx & 511) >> 3, c8 = (idx & 7) * 8;
            if (idx < 512) cp_async16(sK + (r * ATS + c8) * 2, kb + (size_t)r * kvs + c8);
            else           cp_async16(sV + (r * ATS + c8) * 2, vb + (size_t)r * kvs + c8);
        }
        if (tid < 64) MD[st][tid] = (kmask[b * LL + k0 + tid] == 0.f) ? -1e30f : 0.f;
        cp_commit();
    };

    load_kv(0, 0);

    float co[8][4];
#pragma unroll
    for (int nt = 0; nt < 8; nt++)
#pragma unroll
        for (int i = 0; i < 4; i++) co[nt][i] = 0.f;
    float m0 = -1e30f, m1 = -1e30f, l0 = 0.f, l1 = 0.f;
    const int c0 = (lane & 3) * 2;

    for (int kt = 0; kt < NT; kt++) {
        const int st = kt & 1;
        __syncthreads();
        if (kt + 1 < NT) {
            load_kv(kt + 1, st ^ 1);
            cp_wait<1>();
        } else {
            cp_wait<0>();
        }
        __syncthreads();

        const uint32_t sK = sK0 + st * 64 * ATS * 2;
        const uint32_t sV = sV0 + st * 64 * ATS * 2;

        // ---- S = Q K^T ----
        float cs[8][4];
#pragma unroll
        for (int nt = 0; nt < 8; nt++)
#pragma unroll
            for (int i = 0; i < 4; i++) cs[nt][i] = 0.f;
#pragma unroll
        for (int kc = 0; kc < 4; kc++) {
            uint32_t bk[4][4];
#pragma unroll
            for (int np = 0; np < 4; np++) {
                uint32_t addr = sK + (((np * 16 + (lane & 7) + ((lane >> 4) << 3)) * ATS)
                                      + kc * 16 + (((lane >> 3) & 1) << 3)) * 2;
                ldm_x4(bk[np], addr);
            }
#pragma unroll
            for (int nt = 0; nt < 8; nt++)
                mma16816(cs[nt], aq[kc], bk[nt >> 1] + (nt & 1) * 2);
        }

        // ---- online softmax ----
        float sv[8][4];
        float mx0 = -1e30f, mx1 = -1e30f;
#pragma unroll
        for (int nt = 0; nt < 8; nt++) {
            float a0 = MD[st][nt * 8 + c0], a1 = MD[st][nt * 8 + c0 + 1];
            sv[nt][0] = cs[nt][0] + a0;
            sv[nt][1] = cs[nt][1] + a1;
            sv[nt][2] = cs[nt][2] + a0;
            sv[nt][3] = cs[nt][3] + a1;
            mx0 = fmaxf(mx0, fmaxf(sv[nt][0], sv[nt][1]));
            mx1 = fmaxf(mx1, fmaxf(sv[nt][2], sv[nt][3]));
        }
        mx0 = fmaxf(mx0, __shfl_xor_sync(0xffffffffu, mx0, 1));
        mx0 = fmaxf(mx0, __shfl_xor_sync(0xffffffffu, mx0, 2));
        mx1 = fmaxf(mx1, __shfl_xor_sync(0xffffffffu, mx1, 1));
        mx1 = fmaxf(mx1, __shfl_xor_sync(0xffffffffu, mx1, 2));
        float mn0 = fmaxf(m0, mx0), mn1 = fmaxf(m1, mx1);
        float cr0 = __expf(m0 - mn0), cr1 = __expf(m1 - mn1);
        l0 *= cr0; l1 *= cr1;
#pragma unroll
        for (int nt = 0; nt < 8; nt++) {
            co[nt][0] *= cr0; co[nt][1] *= cr0;
            co[nt][2] *= cr1; co[nt][3] *= cr1;
        }
        float ps0 = 0.f, ps1 = 0.f;
        uint32_t ph[8][2];
#pragma unroll
        for (int nt = 0; nt < 8; nt++) {
            float p0 = __expf(sv[nt][0] - mn0);
            float p1 = __expf(sv[nt][1] - mn0);
            float p2 = __expf(sv[nt][2] - mn1);
            float p3 = __expf(sv[nt][3] - mn1);
            ps0 += p0 + p1; ps1 += p2 + p3;
            ph[nt][0] = packh2(p0, p1);
            ph[nt][1] = packh2(p2, p3);
        }
        ps0 += __shfl_xor_sync(0xffffffffu, ps0, 1);
        ps0 += __shfl_xor_sync(0xffffffffu, ps0, 2);
        ps1 += __shfl_xor_sync(0xffffffffu, ps1, 1);
        ps1 += __shfl_xor_sync(0xffffffffu, ps1, 2);
        l0 += ps0; l1 += ps1;
        m0 = mn0; m1 = mn1;

        // ---- O += P V ----
#pragma unroll
        for (int kc = 0; kc < 4; kc++) {
            uint32_t bv[4][4];
#pragma unroll
            for (int np = 0; np < 4; np++) {
                uint32_t addr = sV + (((kc * 16 + (lane & 7) + (((lane >> 3) & 1) << 3)) * ATS)
                                      + np * 16 + ((lane >> 4) << 3)) * 2;
                ldm_x4_t(bv[np], addr);
            }
            uint32_t a[4] = { ph[2 * kc][0], ph[2 * kc][1], ph[2 * kc + 1][0], ph[2 * kc + 1][1] };
#pragma unroll
            for (int nt = 0; nt < 8; nt++)
                mma16816(co[nt], a, bv[nt >> 1] + (nt & 1) * 2);
        }
    }

    float inv0 = 1.f / l0, inv1 = 1.f / l1;
    __half* ob = out + ((size_t)(b * LL + q0 + mwb)) * DD + h * HDIM;
    const int r0 = lane >> 2;
#pragma unroll
    for (int nt = 0; nt < 8; nt++) {
        int col = nt * 8 + c0;
        *(__half2*)(ob + (size_t)r0 * DD + col)       = __floats2half2_rn(co[nt][0] * inv0, co[nt][1] * inv0);
        *(__half2*)(ob + (size_t)(r0 + 8) * DD + col) = __floats2half2_rn(co[nt][2] * inv1, co[nt][3] * inv1);
    }
}

// ---------------- LayerNorm (input already has residual+mask applied) ----------------
__global__ void ln_kernel(const float* __restrict__ y,
                          const float* __restrict__ gam, const float* __restrict__ bet,
                          float* __restrict__ xout, __half* __restrict__ xouth) {
    __shared__ float red[4];
    const int row = blockIdx.x;
    const int tid = threadIdx.x;
    const float* yr = y + (size_t)row * DD;

    float vals[4];
    float s = 0.f;
#pragma unroll
    for (int i = 0; i < 4; i++) {
        int idx = tid + i * 128;
        vals[i] = yr[idx];
        s += vals[i];
    }
#pragma unroll
    for (int off = 16; off > 0; off >>= 1) s += __shfl_down_sync(0xffffffffu, s, off);
    if ((tid & 31) == 0) red[tid >> 5] = s;
    __syncthreads();
    float mean = (red[0] + red[1] + red[2] + red[3]) * (1.f / DD);

    float s2 = 0.f;
#pragma unroll
    for (int i = 0; i < 4; i++) {
        float d = vals[i] - mean;
        s2 += d * d;
    }
    __syncthreads();
#pragma unroll
    for (int off = 16; off > 0; off >>= 1) s2 += __shfl_down_sync(0xffffffffu, s2, off);
    if ((tid & 31) == 0) red[tid >> 5] = s2;
    __syncthreads();
    float var = (red[0] + red[1] + red[2] + red[3]) * (1.f / DD);
    float inv = rsqrtf(var + 1e-5f);

    float* xo = xout + (size_t)row * DD;
    __half* xoh = xouth + (size_t)row * DD;
#pragma unroll
    for (int i = 0; i < 4; i++) {
        int idx = tid + i * 128;
        float r = (vals[i] - mean) * inv * gam[idx] + bet[idx];
        xo[idx] = r;
        xoh[idx] = __float2half(r);
    }
}

// ---------------- launch ----------------
extern "C" void kernel_launch(void* const* d_in, const int* in_sizes, int n_in,
                              void* d_out, int out_size) {
    const float* query = (const float*)d_in[0];
    const float* key   = (const float*)d_in[1];
    const float* qmask = (const float*)d_in[2];
    const float* kmask = (const float*)d_in[3];
    const float* bq = (const float*)d_in[5];
    const float* bk = (const float*)d_in[7];
    const float* bv = (const float*)d_in[9];
    const float* bo = (const float*)d_in[11];
    const float* b1 = (const float*)d_in[13];
    const float* b2 = (const float*)d_in[15];
    const float* ln1g = (const float*)d_in[16];
    const float* ln1b = (const float*)d_in[17];
    const float* ln2g = (const float*)d_in[18];
    const float* ln2b = (const float*)d_in[19];
    float* out = (float*)d_out;

    float *px, *pt, *pbkv;
    int* pkt;
    __half *pxh, *pkh, *pah, *phh, *pkv;
    __half *wq, *wo, *wkv, *w1, *w2;
    cudaGetSymbolAddress((void**)&px, g_x);
    cudaGetSymbolAddress((void**)&pt, g_t);
    cudaGetSymbolAddress((void**)&pbkv, g_bkv);
    cudaGetSymbolAddress((void**)&pkt, g_kt);
    cudaGetSymbolAddress((void**)&pxh, g_xh);
    cudaGetSymbolAddress((void**)&pkh, g_kh);
    cudaGetSymbolAddress((void**)&pah, g_ah);
    cudaGetSymbolAddress((void**)&phh, g_hh);
    cudaGetSymbolAddress((void**)&pkv, g_kvp);
    cudaGetSymbolAddress((void**)&wq, g_wqh);
    cudaGetSymbolAddress((void**)&wo, g_woh);
    cudaGetSymbolAddress((void**)&wkv, g_wkvh);
    cudaGetSymbolAddress((void**)&w1, g_w1h);
    cudaGetSymbolAddress((void**)&w2, g_w2h);

    cudaFuncSetAttribute(gemm_tc<false, true, false>, cudaFuncAttributeMaxDynamicSharedMemorySize, GS3);
    cudaFuncSetAttribute(gemm_tc<false, false, true>, cudaFuncAttributeMaxDynamicSharedMemorySize, GS3);
    cudaFuncSetAttribute(gemm_tc<true, true, false>,  cudaFuncAttributeMaxDynamicSharedMemorySize, GS3);

    // ---- startup ----
    convert_all<<<(CVT_KEY + 255) / 256, 256>>>(
        (const float*)d_in[4], (const float*)d_in[10], (const float*)d_in[12],
        (const float*)d_in[14], key, wq, wo, w1, w2, pkh);
    wkv_f2h<<<(NLAYERS * 131072 + 255) / 256, 256>>>((const float*)d_in[6], (const float*)d_in[8], wkv);
    copy_both_kernel<<<(ROWS * DD / 4 + 255) / 256, 256>>>(query, px, pxh, ROWS * DD / 4);
    misc_kernel<<<28, 256>>>(bk, bv, pbkv, kmask, pkt);

    const dim3 gemm_blk(256);
    const dim3 gD(DD / 128, ROWS / 128);
    const dim3 gF(FF / 128, ROWS / 128);
    const dim3 gKV(KVW / 128, ROWS / 128);
    const dim3 gAttn(LL / 64, HH, BB);

    gemm_tc<false, true, false><<<gKV, gemm_blk, GS3>>>(pkh, wkv, pbkv, pkv, ROWS, KVW, DD, nullptr, nullptr);

    for (int li = 0; li < NLAYERS; li++) {
        const size_t wED = (size_t)li * DD * DD;
        const size_t wFD = (size_t)li * FF * DD;

        attn_tc<<<gAttn, 128>>>(pxh, wq + wED, bq + li * DD,
                                pkv + li * 2 * DD, pkv + li * 2 * DD + DD, KVW,
                                pkt, kmask, pah);

        gemm_tc<false, false, true><<<gD, gemm_blk, GS3>>>(pah, wo + wED, bo + li * DD, pt, ROWS, DD, DD, px, qmask);
        ln_kernel<<<ROWS, 128>>>(pt, ln1g + li * DD, ln1b + li * DD, px, pxh);

        gemm_tc<true, true, false><<<gF, gemm_blk, GS3>>>(pxh, w1 + wFD, b1 + li * FF, phh, ROWS, FF, DD, nullptr, nullptr);
        gemm_tc<false, false, true><<<gD, gemm_blk, GS3>>>(phh, w2 + wFD, b2 + li * DD, pt, ROWS, DD, FF, px, qmask);

        float* dst = (li == NLAYERS - 1) ? out : px;
        ln_kernel<<<ROWS, 128>>>(pt, ln2g + li * DD, ln2b + li * DD, dst, pxh);
    }
}